// round 10
// baseline (speedup 1.0000x reference)
#include <cuda_runtime.h>
#include <cuda_fp16.h>
#include <math.h>
#include <stdint.h>

#define D_    1024
#define BATCH 4
#define NB_   2048
#define NCTX  2048
#define H_    16
#define HD_   64
#define E_    8
#define NTOK  8192

// ---------------- scratch (device globals; no allocation allowed) ----------------
// Split planes: uint2 {hi half2, lo half2} per column pair.
__device__ uint2 g_tokS[NTOK * 512];
__device__ uint2 g_ctxACS[NTOK * 512];
__device__ uint2 g_qS[NTOK * 512];
__device__ uint2 g_kvS[NTOK * 1024];
__device__ uint2 g_attnS[NTOK * 512];
__device__ uint2 g_ctxBS[NTOK * 512];
__device__ uint2 g_inwS[3072 * 512];
__device__ uint2 g_opwS[1024 * 512];
__device__ uint2 g_gw1S[1024 * 1536];
__device__ float g_proj[NTOK * D_];
__device__ float g_hidden[NTOK * D_];
__device__ float g_logits[NTOK * E_];
__device__ float g_emb[BATCH * D_];
__device__ float g_h2[BATCH * 2 * D_];
__device__ float g_temb[BATCH * D_];
__device__ float g_tec[BATCH * D_];
__device__ float g_loadp[32 * E_];

// ================= fp16 split helpers ============================================
__device__ __forceinline__ void split_pair(float x, float y, uint32_t& hw, uint32_t& lw)
{
    __half2 h = __floats2half2_rn(x, y);
    hw = *reinterpret_cast<uint32_t*>(&h);
    float rx = x - __low2float(h);
    float ry = y - __high2float(h);
    __half2 l = __floats2half2_rn(rx, ry);
    lw = *reinterpret_cast<uint32_t*>(&l);
}
__device__ __forceinline__ uint32_t pack_h(float x, float y)
{
    __half2 h = __floats2half2_rn(x, y);
    return *reinterpret_cast<uint32_t*>(&h);
}
__device__ __forceinline__ void mma16(float* c, uint32_t a0, uint32_t a1, uint32_t a2,
                                      uint32_t a3, uint32_t b0, uint32_t b1)
{
    asm volatile(
        "mma.sync.aligned.m16n8k16.row.col.f32.f16.f16.f32 "
        "{%0,%1,%2,%3},{%4,%5,%6,%7},{%8,%9},{%0,%1,%2,%3};\n"
        : "+f"(c[0]), "+f"(c[1]), "+f"(c[2]), "+f"(c[3])
        : "r"(a0), "r"(a1), "r"(a2), "r"(a3), "r"(b0), "r"(b1));
}
__device__ __forceinline__ uint32_t pick_h(uint32_t w, int sel)
{
    return sel ? (w >> 16) : (w & 0xffffu);
}

// ---------------- fp32 -> split plane converters ---------------------------------
__global__ void __launch_bounds__(256) split_kernel(
    const float* __restrict__ X, uint2* __restrict__ S)
{
    const int i = blockIdx.x * 256 + threadIdx.x;
    float2 x = ((const float2*)X)[i];
    uint32_t h, l;
    split_pair(x.x, x.y, h, l);
    S[i] = make_uint2(h, l);
}

__global__ void __launch_bounds__(256) concat_kernel(
    const float* __restrict__ A, const float* __restrict__ C, uint2* __restrict__ S)
{
    const int row = blockIdx.x;
    const int b = row >> 11, j = row & 2047;
    const float* src = (j < 1024) ? (A + ((long)b * 1024 + j) * D_)
                                  : (C + ((long)b * 1024 + (j - 1024)) * D_);
    uint2* dst = S + (long)row * 512;
    const int idx = threadIdx.x;
    float4 v = ((const float4*)src)[idx];
    uint32_t h0, l0, h1, l1;
    split_pair(v.x, v.y, h0, l0);
    split_pair(v.z, v.w, h1, l1);
    dst[idx * 2] = make_uint2(h0, l0);
    dst[idx * 2 + 1] = make_uint2(h1, l1);
}

// Buffer (uint32 words): Ah[2048] Al[2048] Bh[1024] Bl[1024] = 6144 words; x2 buffers
#define HGEMM_SMEM (2 * 6144 * 4)

// ============= fp16-split mma GEMM on pre-split planes ===========================
// C(MxN) = A(MxK)*B(NxK)^T + epilogue. grid=(N/64, M/128), 128 threads.
// NPROD=3: AhBh + AhBl + AlBh (~2^-22)   NPROD=2: AhBh + AlBh (~2^-12)
// NPROD=1: AhBh (~2^-10; residual-damped path only)
// OUTS=1: write split-plane output CS instead of float C.
template <int NPROD, bool ACCUM, bool RELU, bool OUTS>
__global__ void __launch_bounds__(128, 3) hgemm_nt(
    int N, int K,
    const uint2* __restrict__ AS, int lda2,
    const uint2* __restrict__ BS, int ldb2,
    float* __restrict__ C, uint2* __restrict__ CS,
    const float* __restrict__ colBias,
    const float* __restrict__ batchBias)
{
    extern __shared__ uint32_t smw[];
    const int tid = threadIdx.x, wid = tid >> 5, lane = tid & 31;
    const int g = lane >> 2, tg = lane & 3;
    const int bm = blockIdx.y * 128, bn = blockIdx.x * 64;
    const int wm = wid & 1, wn = wid >> 1;

    float c[4][4][4];
#pragma unroll
    for (int mi = 0; mi < 4; mi++)
#pragma unroll
        for (int ni = 0; ni < 4; ni++)
#pragma unroll
            for (int e = 0; e < 4; e++) c[mi][ni][e] = 0.f;

    uint2 a_st[4][4];
    uint2 b_st[4][2];

    const uint2* Abase = AS + (long)bm * lda2;
    const uint2* Bbase = BS + (long)bn * ldb2;
    const int nchunk = K >> 5;

    auto ldg_chunk = [&](int c0) {
#pragma unroll
        for (int i = 0; i < 4; i++) {
            const int gA = wid * 4 + i;
            const int mt = gA >> 1, ks = gA & 1;
            const uint2* ap = Abase + (long)(mt * 16 + g) * lda2
                              + ((c0 + ks * 16) >> 1) + tg;
            a_st[i][0] = ap[0];
            a_st[i][1] = ap[8 * lda2];
            a_st[i][2] = ap[4];
            a_st[i][3] = ap[8 * lda2 + 4];
        }
#pragma unroll
        for (int i = 0; i < 4; i++) {
            const int gB = wid * 4 + i;
            const int nt = gB >> 1, ks = gB & 1;
            const uint2* bp = Bbase + (long)(nt * 8 + g) * ldb2
                              + ((c0 + ks * 16) >> 1) + tg;
            b_st[i][0] = bp[0];
            b_st[i][1] = bp[4];
        }
    };

    auto sts_chunk = [&](uint32_t* buf) {
#pragma unroll
        for (int i = 0; i < 4; i++) {
            const int gA = wid * 4 + i;
            *(uint4*)(buf + gA * 128 + lane * 4) =
                make_uint4(a_st[i][0].x, a_st[i][1].x, a_st[i][2].x, a_st[i][3].x);
            if (NPROD >= 2)
                *(uint4*)(buf + 2048 + gA * 128 + lane * 4) =
                    make_uint4(a_st[i][0].y, a_st[i][1].y, a_st[i][2].y, a_st[i][3].y);
        }
#pragma unroll
        for (int i = 0; i < 4; i++) {
            const int gB = wid * 4 + i;
            *(uint2*)(buf + 4096 + gB * 64 + lane * 2) =
                make_uint2(b_st[i][0].x, b_st[i][1].x);
            if (NPROD == 3)
                *(uint2*)(buf + 5120 + gB * 64 + lane * 2) =
                    make_uint2(b_st[i][0].y, b_st[i][1].y);
        }
    };

    auto mma_chunk = [&](const uint32_t* buf) {
#pragma unroll
        for (int ks = 0; ks < 2; ks++) {
            uint4 ah[4];
            uint2 bh[4];
#pragma unroll
            for (int mi = 0; mi < 4; mi++) {
                const int mt = wm * 4 + mi;
                ah[mi] = *(const uint4*)(buf + (mt * 2 + ks) * 128 + lane * 4);
            }
#pragma unroll
            for (int ni = 0; ni < 4; ni++) {
                const int nt = wn * 4 + ni;
                bh[ni] = *(const uint2*)(buf + 4096 + (nt * 2 + ks) * 64 + lane * 2);
            }
#pragma unroll
            for (int mi = 0; mi < 4; mi++)
#pragma unroll
                for (int ni = 0; ni < 4; ni++)
                    mma16(c[mi][ni], ah[mi].x, ah[mi].y, ah[mi].z, ah[mi].w,
                          bh[ni].x, bh[ni].y);
            if (NPROD >= 2) {
                uint4 al[4];
#pragma unroll
                for (int mi = 0; mi < 4; mi++) {
                    const int mt = wm * 4 + mi;
                    al[mi] = *(const uint4*)(buf + 2048 + (mt * 2 + ks) * 128 + lane * 4);
                }
#pragma unroll
                for (int mi = 0; mi < 4; mi++)
#pragma unroll
                    for (int ni = 0; ni < 4; ni++)
                        mma16(c[mi][ni], al[mi].x, al[mi].y, al[mi].z, al[mi].w,
                              bh[ni].x, bh[ni].y);
            }
            if (NPROD == 3) {
                uint2 bl[4];
#pragma unroll
                for (int ni = 0; ni < 4; ni++) {
                    const int nt = wn * 4 + ni;
                    bl[ni] = *(const uint2*)(buf + 5120 + (nt * 2 + ks) * 64 + lane * 2);
                }
#pragma unroll
                for (int mi = 0; mi < 4; mi++)
#pragma unroll
                    for (int ni = 0; ni < 4; ni++)
                        mma16(c[mi][ni], ah[mi].x, ah[mi].y, ah[mi].z, ah[mi].w,
                              bl[ni].x, bl[ni].y);
            }
        }
    };

    ldg_chunk(0);
    sts_chunk(smw);
    __syncthreads();
    for (int cc = 0; cc < nchunk; cc++) {
        if (cc + 1 < nchunk) ldg_chunk((cc + 1) << 5);
        mma_chunk(smw + (cc & 1) * 6144);
        if (cc + 1 < nchunk) sts_chunk(smw + ((cc + 1) & 1) * 6144);
        __syncthreads();
    }

    // ---- epilogue ----
    const int bb = bm >> 11;
#pragma unroll
    for (int mi = 0; mi < 4; mi++) {
        const int row = bm + (wm * 4 + mi) * 16 + g;
#pragma unroll
        for (int ni = 0; ni < 4; ni++) {
            const int col = bn + wn * 32 + ni * 8 + 2 * tg;
            float2 v0 = make_float2(c[mi][ni][0], c[mi][ni][1]);
            float2 v1 = make_float2(c[mi][ni][2], c[mi][ni][3]);
            if (colBias) {
                float2 cb = *(const float2*)(colBias + col);
                v0.x += cb.x; v0.y += cb.y;
                v1.x += cb.x; v1.y += cb.y;
            }
            if (batchBias) {
                float2 pb = *(const float2*)(batchBias + (long)bb * N + col);
                v0.x += pb.x; v0.y += pb.y;
                v1.x += pb.x; v1.y += pb.y;
            }
            if (OUTS) {
                uint32_t h, l;
                split_pair(v0.x, v0.y, h, l);
                CS[(long)row * (N >> 1) + (col >> 1)] = make_uint2(h, l);
                split_pair(v1.x, v1.y, h, l);
                CS[(long)(row + 8) * (N >> 1) + (col >> 1)] = make_uint2(h, l);
            } else {
                float* g0 = C + (long)row * N + col;
                float* g1 = C + (long)(row + 8) * N + col;
                if (ACCUM) {
                    float2 o0 = *(const float2*)g0;
                    float2 o1 = *(const float2*)g1;
                    v0.x += o0.x; v0.y += o0.y;
                    v1.x += o1.x; v1.y += o1.y;
                }
                if (RELU) {
                    v0.x = fmaxf(v0.x, 0.f); v0.y = fmaxf(v0.y, 0.f);
                    v1.x = fmaxf(v1.x, 0.f); v1.y = fmaxf(v1.y, 0.f);
                }
                *(float2*)g0 = v0;
                *(float2*)g1 = v1;
            }
        }
    }
}

// ============= flash attention, hi-only everywhere (1-product) ===================
// grid=(NB/64, B*H), 128 threads (4 warps x 16 q-rows). KV tiles of 64 keys.
// QK = Qh*Kh ; PV = Ph*Vh  (residual-damped; measured damping ~1e-3 S->out).
// smem per buffer (words): Kh[2048] Vh[2048]; double buffered = 32KB.
#define FLASH_SMEM (2 * 4096 * 4)
__global__ void __launch_bounds__(128, 3) flash_kernel(
    const uint2* __restrict__ QS, const uint2* __restrict__ KVS,
    uint2* __restrict__ OS)
{
    extern __shared__ uint32_t smw[];
    const int tid = threadIdx.x, wid = tid >> 5, lane = tid & 31;
    const int g = lane >> 2, tg = lane & 3;
    const int bh = blockIdx.y, b = bh >> 4, h = bh & 15;
    const int q0 = blockIdx.x * 64;
    const int qrow = q0 + wid * 16;

    uint32_t Qh[4][4];
    {
        const uint2* qb = QS + (long)(b * NB_ + qrow + g) * 512 + h * 32 + tg;
#pragma unroll
        for (int ks = 0; ks < 4; ks++) {
            Qh[ks][0] = qb[ks * 8].x;
            Qh[ks][1] = qb[ks * 8 + 8 * 512].x;
            Qh[ks][2] = qb[ks * 8 + 4].x;
            Qh[ks][3] = qb[ks * 8 + 8 * 512 + 4].x;
        }
    }

    float m0 = -1e30f, m1 = -1e30f, l0 = 0.f, l1 = 0.f;
    float o[8][4];
#pragma unroll
    for (int nt = 0; nt < 8; nt++)
#pragma unroll
        for (int e = 0; e < 4; e++) o[nt][e] = 0.f;

    const uint2* kvb = KVS + (long)b * NCTX * 1024;
    const int vsel = g & 1;

    for (int kt = 0; kt < NCTX; kt += 64) {
        uint32_t* buf = smw + ((kt >> 6) & 1) * 4096;

        // ---- stage K (hi only) ----
#pragma unroll
        for (int i = 0; i < 8; i++) {
            const int gk = wid * 8 + i;
            const int nt = gk >> 2, ks = gk & 3;
            const uint2* kp = kvb + (long)(kt + nt * 8 + g) * 1024 + h * 32 + ks * 8 + tg;
            uint2 u0 = kp[0];
            uint2 u1 = kp[4];
            *(uint2*)(buf + gk * 64 + lane * 2) = make_uint2(u0.x, u1.x);
        }
        // ---- stage V (hi only) ----
#pragma unroll
        for (int i = 0; i < 8; i++) {
            const int gv = wid * 8 + i;
            const int nt = gv >> 2, ks = gv & 3;
            const long r0 = kt + ks * 16 + 2 * tg;
            const int vcol = 512 + h * 32 + nt * 4 + (g >> 1);
            uint2 u0 = kvb[r0 * 1024 + vcol];
            uint2 u1 = kvb[(r0 + 1) * 1024 + vcol];
            uint2 u2 = kvb[(r0 + 8) * 1024 + vcol];
            uint2 u3 = kvb[(r0 + 9) * 1024 + vcol];
            uint32_t hw0 = pick_h(u0.x, vsel) | (pick_h(u1.x, vsel) << 16);
            uint32_t hw1 = pick_h(u2.x, vsel) | (pick_h(u3.x, vsel) << 16);
            *(uint2*)(buf + 2048 + gv * 64 + lane * 2) = make_uint2(hw0, hw1);
        }
        __syncthreads();

        // ---- QK^T : Qh * Kh ----
        float S[8][4];
#pragma unroll
        for (int nt = 0; nt < 8; nt++)
#pragma unroll
            for (int e = 0; e < 4; e++) S[nt][e] = 0.f;

#pragma unroll
        for (int ks = 0; ks < 4; ks++) {
            uint2 kh[8];
#pragma unroll
            for (int nt = 0; nt < 8; nt++)
                kh[nt] = *(const uint2*)(buf + (nt * 4 + ks) * 64 + lane * 2);
#pragma unroll
            for (int nt = 0; nt < 8; nt++)
                mma16(S[nt], Qh[ks][0], Qh[ks][1], Qh[ks][2], Qh[ks][3],
                      kh[nt].x, kh[nt].y);
        }

        // ---- online softmax ----
        float mx0 = -1e30f, mx1 = -1e30f;
#pragma unroll
        for (int nt = 0; nt < 8; nt++) {
            S[nt][0] *= 0.125f; S[nt][1] *= 0.125f;
            S[nt][2] *= 0.125f; S[nt][3] *= 0.125f;
            mx0 = fmaxf(mx0, fmaxf(S[nt][0], S[nt][1]));
            mx1 = fmaxf(mx1, fmaxf(S[nt][2], S[nt][3]));
        }
        mx0 = fmaxf(mx0, __shfl_xor_sync(0xffffffffu, mx0, 1));
        mx0 = fmaxf(mx0, __shfl_xor_sync(0xffffffffu, mx0, 2));
        mx1 = fmaxf(mx1, __shfl_xor_sync(0xffffffffu, mx1, 1));
        mx1 = fmaxf(mx1, __shfl_xor_sync(0xffffffffu, mx1, 2));
        const float mn0 = fmaxf(m0, mx0), mn1 = fmaxf(m1, mx1);
        const float al0 = __expf(m0 - mn0), al1 = __expf(m1 - mn1);
        m0 = mn0; m1 = mn1;
        float s0 = 0.f, s1 = 0.f;
#pragma unroll
        for (int nt = 0; nt < 8; nt++) {
            S[nt][0] = __expf(S[nt][0] - mn0); s0 += S[nt][0];
            S[nt][1] = __expf(S[nt][1] - mn0); s0 += S[nt][1];
            S[nt][2] = __expf(S[nt][2] - mn1); s1 += S[nt][2];
            S[nt][3] = __expf(S[nt][3] - mn1); s1 += S[nt][3];
        }
        s0 += __shfl_xor_sync(0xffffffffu, s0, 1);
        s0 += __shfl_xor_sync(0xffffffffu, s0, 2);
        s1 += __shfl_xor_sync(0xffffffffu, s1, 1);
        s1 += __shfl_xor_sync(0xffffffffu, s1, 2);
        l0 = l0 * al0 + s0;
        l1 = l1 * al1 + s1;
#pragma unroll
        for (int nt = 0; nt < 8; nt++) {
            o[nt][0] *= al0; o[nt][1] *= al0;
            o[nt][2] *= al1; o[nt][3] *= al1;
        }

        // ---- P -> A-fragments (hi only) ----
        uint32_t Ph[4][4];
#pragma unroll
        for (int ks = 0; ks < 4; ks++) {
            Ph[ks][0] = pack_h(S[2 * ks][0], S[2 * ks][1]);
            Ph[ks][1] = pack_h(S[2 * ks][2], S[2 * ks][3]);
            Ph[ks][2] = pack_h(S[2 * ks + 1][0], S[2 * ks + 1][1]);
            Ph[ks][3] = pack_h(S[2 * ks + 1][2], S[2 * ks + 1][3]);
        }

        // ---- P V : Ph * Vh ----
#pragma unroll
        for (int ks = 0; ks < 4; ks++) {
            uint2 vh[8];
#pragma unroll
            for (int nt = 0; nt < 8; nt++)
                vh[nt] = *(const uint2*)(buf + 2048 + (nt * 4 + ks) * 64 + lane * 2);
#pragma unroll
            for (int nt = 0; nt < 8; nt++)
                mma16(o[nt], Ph[ks][0], Ph[ks][1], Ph[ks][2], Ph[ks][3],
                      vh[nt].x, vh[nt].y);
        }
    }

    const float inv0 = 1.0f / l0, inv1 = 1.0f / l1;
    uint2* op0 = OS + (long)(b * NB_ + qrow + g) * 512 + h * 32 + tg;
    uint2* op1 = op0 + 8 * 512;
#pragma unroll
    for (int nt = 0; nt < 8; nt++) {
        uint32_t h0, l0w;
        split_pair(o[nt][0] * inv0, o[nt][1] * inv0, h0, l0w);
        op0[nt * 4] = make_uint2(h0, l0w);
        split_pair(o[nt][2] * inv1, o[nt][3] * inv1, h0, l0w);
        op1[nt * 4] = make_uint2(h0, l0w);
    }
}

// ---------------- residual + layernorm -> split plane ----------------------------
__global__ void __launch_bounds__(256) ln_kernel(
    const float* __restrict__ X, const float* __restrict__ R,
    const float* __restrict__ gam, const float* __restrict__ bet,
    uint2* __restrict__ YS)
{
    __shared__ float red[8];
    const int row = blockIdx.x, tid = threadIdx.x;
    const float2* x = (const float2*)(X + (long)row * D_);
    const float2* rr = (const float2*)(R + (long)row * D_);
    float2 v[2];
    float s = 0.f;
#pragma unroll
    for (int i = 0; i < 2; i++) {
        int p = tid + 256 * i;
        float2 a = x[p], b = rr[p];
        v[i].x = a.x + b.x;
        v[i].y = a.y + b.y;
        s += v[i].x + v[i].y;
    }
#pragma unroll
    for (int off = 16; off > 0; off >>= 1) s += __shfl_xor_sync(0xffffffffu, s, off);
    if ((tid & 31) == 0) red[tid >> 5] = s;
    __syncthreads();
    float tot = red[0] + red[1] + red[2] + red[3] + red[4] + red[5] + red[6] + red[7];
    float mu = tot * (1.0f / 1024.0f);
    __syncthreads();
    float s2 = 0.f;
#pragma unroll
    for (int i = 0; i < 2; i++) {
        float dx = v[i].x - mu, dy = v[i].y - mu;
        s2 += dx * dx + dy * dy;
    }
#pragma unroll
    for (int off = 16; off > 0; off >>= 1) s2 += __shfl_xor_sync(0xffffffffu, s2, off);
    if ((tid & 31) == 0) red[tid >> 5] = s2;
    __syncthreads();
    float tot2 = red[0] + red[1] + red[2] + red[3] + red[4] + red[5] + red[6] + red[7];
    float rstd = rsqrtf(tot2 * (1.0f / 1024.0f) + 1e-5f);
#pragma unroll
    for (int i = 0; i < 2; i++) {
        int p = tid + 256 * i;
        float2 gg = ((const float2*)gam)[p];
        float2 bb = ((const float2*)bet)[p];
        float y0 = (v[i].x - mu) * rstd * gg.x + bb.x;
        float y1 = (v[i].y - mu) * rstd * gg.y + bb.y;
        uint32_t h, l;
        split_pair(y0, y1, h, l);
        YS[(long)row * 512 + p] = make_uint2(h, l);
    }
}

// ---------------- generic warp-dot: Y[b][j] = act(dot(X[b], W[j]) + b1 + b2) ------
template <int ACT>
__global__ void __launch_bounds__(256) rowdot(
    const float* __restrict__ X, const float* __restrict__ W, int ldw,
    const float* __restrict__ b1, const float* __restrict__ b2,
    float* __restrict__ Y, int Kd, int J)
{
    const int b = blockIdx.x;
    const int w = threadIdx.x >> 5, lane = threadIdx.x & 31;
    const int j = blockIdx.y * 8 + w;
    const float* x = X + (long)b * Kd;
    const float* wr = W + (long)j * ldw;
    float s = 0.f;
    for (int k = lane * 4; k < Kd; k += 128) {
        float4 xv = *(const float4*)(x + k);
        float4 wv = *(const float4*)(wr + k);
        s += xv.x * wv.x + xv.y * wv.y + xv.z * wv.z + xv.w * wv.w;
    }
#pragma unroll
    for (int off = 16; off > 0; off >>= 1) s += __shfl_xor_sync(0xffffffffu, s, off);
    if (lane == 0) {
        if (b1) s += b1[j];
        if (b2) s += b2[j];
        if (ACT == 1) s = s / (1.f + expf(-s));
        Y[(long)b * J + j] = s;
    }
}

// ---------------- small kernels ---------------------------------------------------
__global__ void emb_kernel(const int* __restrict__ t)
{
    const int b = blockIdx.x, i = threadIdx.x;
    float fr = expf(-9.2103403719761836f * (float)i / 511.0f);
    float arg = (float)t[b] * fr;
    g_emb[b * D_ + i] = sinf(arg);
    g_emb[b * D_ + 512 + i] = cosf(arg);
}

__global__ void __launch_bounds__(256) router_kernel(
    const float* __restrict__ logits, const int* __restrict__ t,
    float* __restrict__ dispatch, float* __restrict__ combine, float* __restrict__ loadp)
{
    __shared__ float sd[8 * 256];
    const int tid = threadIdx.x;
    const int tok = blockIdx.x * 256 + tid;
    const int b = tok >> 11;
    const float tn = (float)t[b] * 0.001f;
    const float tau_inv = 1.0f / (0.5f + 1.5f * tn);

    float p[8];
    float mx = -1e30f;
#pragma unroll
    for (int e = 0; e < 8; e++) { p[e] = logits[tok * 8 + e] * tau_inv; mx = fmaxf(mx, p[e]); }
    float s = 0.f;
#pragma unroll
    for (int e = 0; e < 8; e++) { p[e] = expf(p[e] - mx); s += p[e]; }
    float inv = 1.0f / s;
#pragma unroll
    for (int e = 0; e < 8; e++) p[e] = 0.85f * (p[e] * inv) + 0.01875f;

    const float w = 0.1f + 0.1f * tn;
    float sh = fmaxf(p[0], w);
    float os = 0.f;
#pragma unroll
    for (int e = 1; e < 8; e++) os += p[e];
    float sc = (1.0f - sh) / fmaxf(os, 1e-8f);
    p[0] = sh;
#pragma unroll
    for (int e = 1; e < 8; e++) p[e] *= sc;

    int i1 = 0; float v1 = p[0];
#pragma unroll
    for (int e = 1; e < 8; e++) if (p[e] > v1) { v1 = p[e]; i1 = e; }
    int i2 = -1; float v2 = -1e30f;
#pragma unroll
    for (int e = 0; e < 8; e++) if (e != i1 && p[e] > v2) { v2 = p[e]; i2 = e; }

    float d[8];
#pragma unroll
    for (int e = 0; e < 8; e++) d[e] = 0.f;
    d[i1] = v1; d[i2] = v2;

    const float cap = 0.5f + 0.1f * tn;
    float ext = 0.f, hs = 0.f;
    float hd[8];
#pragma unroll
    for (int e = 0; e < 8; e++) {
        float ex = fmaxf(d[e] - cap, 0.f);
        d[e] -= ex; ext += ex;
        hd[e] = fmaxf(cap - d[e], 0.f); hs += hd[e];
    }
    hs = fmaxf(hs, 1e-8f);
    float ds = 0.f;
#pragma unroll
    for (int e = 0; e < 8; e++) { d[e] += ext * (hd[e] / hs); ds += d[e]; }
    float ci = 1.0f / (ds + 1e-8f);
#pragma unroll
    for (int e = 0; e < 8; e++) {
        dispatch[tok * 8 + e] = d[e];
        combine[tok * 8 + e] = d[e] * ci;
        sd[e * 256 + tid] = d[e];
    }
    __syncthreads();
    if (tid < 8) {
        float acc = 0.f;
        for (int i = 0; i < 256; i++) acc += sd[tid * 256 + i];
        loadp[blockIdx.x * 8 + tid] = acc;
    }
}

__global__ void penalty_kernel(const float* __restrict__ loadp, float* __restrict__ out)
{
    if (threadIdx.x == 0) {
        const float thr = (2048.0f / 7.0f) * 1.5f;
        float pen = 0.f;
        for (int e = 1; e < 8; e++) {
            float l = 0.f;
            for (int blk = 0; blk < 32; blk++) l += loadp[blk * 8 + e];
            l *= 0.25f;
            float x = l - thr;
            if (x > 0.f) pen += x * x;
        }
        out[0] = 0.01f * pen;
    }
}

// ---------------- launch ----------------------------------------------------------
extern "C" void kernel_launch(void* const* d_in, const int* in_sizes, int n_in,
                              void* d_out, int out_size)
{
    const float* tokens = (const float*)d_in[0];
    const float* outA   = (const float*)d_in[1];
    const float* outC   = (const float*)d_in[2];
    const int*   t      = (const int*)d_in[3];
    const float* in_w   = (const float*)d_in[4];
    const float* in_b   = (const float*)d_in[5];
    const float* op_w   = (const float*)d_in[6];
    const float* op_b   = (const float*)d_in[7];
    const float* lng    = (const float*)d_in[8];
    const float* lnb    = (const float*)d_in[9];
    const float* te_w1  = (const float*)d_in[10];
    const float* te_b1  = (const float*)d_in[11];
    const float* te_w2  = (const float*)d_in[12];
    const float* te_b2  = (const float*)d_in[13];
    const float* gw1    = (const float*)d_in[14];
    const float* gb1    = (const float*)d_in[15];
    const float* gw2    = (const float*)d_in[16];
    const float* gb2    = (const float*)d_in[17];
    const float* ebias  = (const float*)d_in[18];
    float* out = (float*)d_out;

    uint2 *p_tokS, *p_ctxACS, *p_qS, *p_kvS, *p_attnS, *p_ctxBS,
          *p_inwS, *p_opwS, *p_gw1S;
    float *p_proj, *p_hidden, *p_logits, *p_emb, *p_h2, *p_temb, *p_tec, *p_loadp;
    cudaGetSymbolAddress((void**)&p_tokS, g_tokS);
    cudaGetSymbolAddress((void**)&p_ctxACS, g_ctxACS);
    cudaGetSymbolAddress((void**)&p_qS, g_qS);
    cudaGetSymbolAddress((void**)&p_kvS, g_kvS);
    cudaGetSymbolAddress((void**)&p_attnS, g_attnS);
    cudaGetSymbolAddress((void**)&p_ctxBS, g_ctxBS);
    cudaGetSymbolAddress((void**)&p_inwS, g_inwS);
    cudaGetSymbolAddress((void**)&p_opwS, g_opwS);
    cudaGetSymbolAddress((void**)&p_gw1S, g_gw1S);
    cudaGetSymbolAddress((void**)&p_proj, g_proj);
    cudaGetSymbolAddress((void**)&p_hidden, g_hidden);
    cudaGetSymbolAddress((void**)&p_logits, g_logits);
    cudaGetSymbolAddress((void**)&p_emb, g_emb);
    cudaGetSymbolAddress((void**)&p_h2, g_h2);
    cudaGetSymbolAddress((void**)&p_temb, g_temb);
    cudaGetSymbolAddress((void**)&p_tec, g_tec);
    cudaGetSymbolAddress((void**)&p_loadp, g_loadp);

    cudaFuncSetAttribute(flash_kernel, cudaFuncAttributeMaxDynamicSharedMemorySize,
                         FLASH_SMEM);
    cudaFuncSetAttribute(hgemm_nt<2, false, false, true>,
                         cudaFuncAttributeMaxDynamicSharedMemorySize, HGEMM_SMEM);
    cudaFuncSetAttribute(hgemm_nt<1, false, false, false>,
                         cudaFuncAttributeMaxDynamicSharedMemorySize, HGEMM_SMEM);
    cudaFuncSetAttribute(hgemm_nt<3, false, false, false>,
                         cudaFuncAttributeMaxDynamicSharedMemorySize, HGEMM_SMEM);
    cudaFuncSetAttribute(hgemm_nt<3, true, true, false>,
                         cudaFuncAttributeMaxDynamicSharedMemorySize, HGEMM_SMEM);

    // ---- time embedding chain ----
    emb_kernel<<<BATCH, 512>>>(t);
    rowdot<1><<<dim3(BATCH, 256), 256>>>(p_emb, te_w1, 1024, te_b1, nullptr, p_h2, 1024, 2048);
    rowdot<0><<<dim3(BATCH, 128), 256>>>(p_h2, te_w2, 2048, te_b2, nullptr, p_temb, 2048, 1024);
    rowdot<0><<<dim3(BATCH, 128), 256>>>(p_temb, gw1 + 2048, 3072, gb1, nullptr, p_tec, 1024, 1024);

    // ---- split inputs/weights into fp16 hi/lo planes ----
    split_kernel<<<NTOK * 2, 256>>>(tokens, p_tokS);
    split_kernel<<<6144, 256>>>(in_w, p_inwS);
    split_kernel<<<2048, 256>>>(op_w, p_opwS);
    split_kernel<<<6144, 256>>>(gw1, p_gw1S);
    concat_kernel<<<NTOK, 256>>>(outA, outC, p_ctxACS);

    // ---- attention path (residual-damped accuracy budget) ----
    hgemm_nt<2, false, false, true><<<dim3(16, 64), 128, HGEMM_SMEM>>>(
        1024, 1024, p_tokS, 512, p_inwS, 512, nullptr, p_qS, in_b, nullptr);
    hgemm_nt<2, false, false, true><<<dim3(32, 64), 128, HGEMM_SMEM>>>(
        2048, 1024, p_ctxACS, 512, p_inwS + 1024 * 512, 512, nullptr, p_kvS,
        in_b + 1024, nullptr);
    flash_kernel<<<dim3(32, BATCH * H_), 128, FLASH_SMEM>>>(p_qS, p_kvS, p_attnS);
    hgemm_nt<1, false, false, false><<<dim3(16, 64), 128, HGEMM_SMEM>>>(
        1024, 1024, p_attnS, 512, p_opwS, 512, p_proj, nullptr, op_b, nullptr);
    ln_kernel<<<NTOK, 256>>>(p_proj, tokens, lng, lnb, p_ctxBS);

    // ---- gate hidden (3-product: logit-critical) ----
    hgemm_nt<3, false, false, false><<<dim3(16, 64), 128, HGEMM_SMEM>>>(
        1024, 1024, p_tokS, 512, p_gw1S, 1536, p_hidden, nullptr, nullptr, p_tec);
    hgemm_nt<3, true, true, false><<<dim3(16, 64), 128, HGEMM_SMEM>>>(
        1024, 1024, p_ctxBS, 512, p_gw1S + 512, 1536, p_hidden, nullptr, nullptr, nullptr);

    // ---- logits + routing ----
    rowdot<0><<<dim3(NTOK, 1), 256>>>(p_hidden, gw2, 1024, gb2, ebias, p_logits, 1024, 8);
    router_kernel<<<32, 256>>>(p_logits, t, out, out + 65536, p_loadp);
    penalty_kernel<<<1, 32>>>(p_loadp, out + 2 * 65536);
}

// round 11
// speedup vs baseline: 1.5215x; 1.5215x over previous
#include <cuda_runtime.h>
#include <cuda_fp16.h>
#include <math.h>
#include <stdint.h>

#define D_    1024
#define BATCH 4
#define NB_   2048
#define NCTX  2048
#define H_    16
#define HD_   64
#define E_    8
#define NTOK  8192

// ---------------- scratch (device globals; no allocation allowed) ----------------
// Split planes: uint2 {hi half2, lo half2} per column pair.
__device__ uint2 g_tokS[NTOK * 512];
__device__ uint2 g_ctxACS[NTOK * 512];
__device__ uint2 g_qS[NTOK * 512];
__device__ uint2 g_kvS[NTOK * 1024];
__device__ uint2 g_attnS[NTOK * 512];
__device__ uint2 g_ctxBS[NTOK * 512];
__device__ uint2 g_inwS[3072 * 512];
__device__ uint2 g_opwS[1024 * 512];
__device__ uint2 g_gw1S[1024 * 1536];
__device__ float g_proj[NTOK * D_];
__device__ float g_hidden[NTOK * D_];
__device__ float g_logits[NTOK * E_];
__device__ float g_emb[BATCH * D_];
__device__ float g_h2[BATCH * 2 * D_];
__device__ float g_temb[BATCH * D_];
__device__ float g_tec[BATCH * D_];
__device__ float g_loadp[32 * E_];

// ================= fp16 split helpers ============================================
__device__ __forceinline__ void split_pair(float x, float y, uint32_t& hw, uint32_t& lw)
{
    __half2 h = __floats2half2_rn(x, y);
    hw = *reinterpret_cast<uint32_t*>(&h);
    float rx = x - __low2float(h);
    float ry = y - __high2float(h);
    __half2 l = __floats2half2_rn(rx, ry);
    lw = *reinterpret_cast<uint32_t*>(&l);
}
__device__ __forceinline__ uint32_t pack_h(float x, float y)
{
    __half2 h = __floats2half2_rn(x, y);
    return *reinterpret_cast<uint32_t*>(&h);
}
__device__ __forceinline__ void mma16(float* c, uint32_t a0, uint32_t a1, uint32_t a2,
                                      uint32_t a3, uint32_t b0, uint32_t b1)
{
    asm volatile(
        "mma.sync.aligned.m16n8k16.row.col.f32.f16.f16.f32 "
        "{%0,%1,%2,%3},{%4,%5,%6,%7},{%8,%9},{%0,%1,%2,%3};\n"
        : "+f"(c[0]), "+f"(c[1]), "+f"(c[2]), "+f"(c[3])
        : "r"(a0), "r"(a1), "r"(a2), "r"(a3), "r"(b0), "r"(b1));
}
__device__ __forceinline__ uint32_t pick_h(uint32_t w, int sel)
{
    return sel ? (w >> 16) : (w & 0xffffu);
}

// ---------------- fp32 -> split plane converters ---------------------------------
__global__ void __launch_bounds__(256) split_kernel(
    const float* __restrict__ X, uint2* __restrict__ S)
{
    const int i = blockIdx.x * 256 + threadIdx.x;
    float2 x = ((const float2*)X)[i];
    uint32_t h, l;
    split_pair(x.x, x.y, h, l);
    S[i] = make_uint2(h, l);
}

__global__ void __launch_bounds__(256) concat_kernel(
    const float* __restrict__ A, const float* __restrict__ C, uint2* __restrict__ S)
{
    const int row = blockIdx.x;
    const int b = row >> 11, j = row & 2047;
    const float* src = (j < 1024) ? (A + ((long)b * 1024 + j) * D_)
                                  : (C + ((long)b * 1024 + (j - 1024)) * D_);
    uint2* dst = S + (long)row * 512;
    const int idx = threadIdx.x;
    float4 v = ((const float4*)src)[idx];
    uint32_t h0, l0, h1, l1;
    split_pair(v.x, v.y, h0, l0);
    split_pair(v.z, v.w, h1, l1);
    dst[idx * 2] = make_uint2(h0, l0);
    dst[idx * 2 + 1] = make_uint2(h1, l1);
}

// Buffer (uint32 words): Ah[2048] Al[2048] Bh[1024] Bl[1024] = 6144 words; x2 buffers
#define HGEMM_SMEM (2 * 6144 * 4)

// ============= fp16-split mma GEMM on pre-split planes ===========================
// C(MxN) = A(MxK)*B(NxK)^T + epilogue. grid=(N/64, M/128), 128 threads.
// NPROD=3: AhBh + AhBl + AlBh (~2^-22)   NPROD=2: AhBh + AlBh (~2^-12)
// NPROD=1: AhBh (~2^-10; residual-damped path only)
// OUTS=1: write split-plane output CS instead of float C.
template <int NPROD, bool ACCUM, bool RELU, bool OUTS>
__global__ void __launch_bounds__(128, 3) hgemm_nt(
    int N, int K,
    const uint2* __restrict__ AS, int lda2,
    const uint2* __restrict__ BS, int ldb2,
    float* __restrict__ C, uint2* __restrict__ CS,
    const float* __restrict__ colBias,
    const float* __restrict__ batchBias)
{
    extern __shared__ uint32_t smw[];
    const int tid = threadIdx.x, wid = tid >> 5, lane = tid & 31;
    const int g = lane >> 2, tg = lane & 3;
    const int bm = blockIdx.y * 128, bn = blockIdx.x * 64;
    const int wm = wid & 1, wn = wid >> 1;

    float c[4][4][4];
#pragma unroll
    for (int mi = 0; mi < 4; mi++)
#pragma unroll
        for (int ni = 0; ni < 4; ni++)
#pragma unroll
            for (int e = 0; e < 4; e++) c[mi][ni][e] = 0.f;

    uint2 a_st[4][4];
    uint2 b_st[4][2];

    const uint2* Abase = AS + (long)bm * lda2;
    const uint2* Bbase = BS + (long)bn * ldb2;
    const int nchunk = K >> 5;

    auto ldg_chunk = [&](int c0) {
#pragma unroll
        for (int i = 0; i < 4; i++) {
            const int gA = wid * 4 + i;
            const int mt = gA >> 1, ks = gA & 1;
            const uint2* ap = Abase + (long)(mt * 16 + g) * lda2
                              + ((c0 + ks * 16) >> 1) + tg;
            a_st[i][0] = ap[0];
            a_st[i][1] = ap[8 * lda2];
            a_st[i][2] = ap[4];
            a_st[i][3] = ap[8 * lda2 + 4];
        }
#pragma unroll
        for (int i = 0; i < 4; i++) {
            const int gB = wid * 4 + i;
            const int nt = gB >> 1, ks = gB & 1;
            const uint2* bp = Bbase + (long)(nt * 8 + g) * ldb2
                              + ((c0 + ks * 16) >> 1) + tg;
            b_st[i][0] = bp[0];
            b_st[i][1] = bp[4];
        }
    };

    auto sts_chunk = [&](uint32_t* buf) {
#pragma unroll
        for (int i = 0; i < 4; i++) {
            const int gA = wid * 4 + i;
            *(uint4*)(buf + gA * 128 + lane * 4) =
                make_uint4(a_st[i][0].x, a_st[i][1].x, a_st[i][2].x, a_st[i][3].x);
            if (NPROD >= 2)
                *(uint4*)(buf + 2048 + gA * 128 + lane * 4) =
                    make_uint4(a_st[i][0].y, a_st[i][1].y, a_st[i][2].y, a_st[i][3].y);
        }
#pragma unroll
        for (int i = 0; i < 4; i++) {
            const int gB = wid * 4 + i;
            *(uint2*)(buf + 4096 + gB * 64 + lane * 2) =
                make_uint2(b_st[i][0].x, b_st[i][1].x);
            if (NPROD == 3)
                *(uint2*)(buf + 5120 + gB * 64 + lane * 2) =
                    make_uint2(b_st[i][0].y, b_st[i][1].y);
        }
    };

    auto mma_chunk = [&](const uint32_t* buf) {
#pragma unroll
        for (int ks = 0; ks < 2; ks++) {
            uint4 ah[4];
            uint2 bh[4];
#pragma unroll
            for (int mi = 0; mi < 4; mi++) {
                const int mt = wm * 4 + mi;
                ah[mi] = *(const uint4*)(buf + (mt * 2 + ks) * 128 + lane * 4);
            }
#pragma unroll
            for (int ni = 0; ni < 4; ni++) {
                const int nt = wn * 4 + ni;
                bh[ni] = *(const uint2*)(buf + 4096 + (nt * 2 + ks) * 64 + lane * 2);
            }
#pragma unroll
            for (int mi = 0; mi < 4; mi++)
#pragma unroll
                for (int ni = 0; ni < 4; ni++)
                    mma16(c[mi][ni], ah[mi].x, ah[mi].y, ah[mi].z, ah[mi].w,
                          bh[ni].x, bh[ni].y);
            if (NPROD >= 2) {
                uint4 al[4];
#pragma unroll
                for (int mi = 0; mi < 4; mi++) {
                    const int mt = wm * 4 + mi;
                    al[mi] = *(const uint4*)(buf + 2048 + (mt * 2 + ks) * 128 + lane * 4);
                }
#pragma unroll
                for (int mi = 0; mi < 4; mi++)
#pragma unroll
                    for (int ni = 0; ni < 4; ni++)
                        mma16(c[mi][ni], al[mi].x, al[mi].y, al[mi].z, al[mi].w,
                              bh[ni].x, bh[ni].y);
            }
            if (NPROD == 3) {
                uint2 bl[4];
#pragma unroll
                for (int ni = 0; ni < 4; ni++) {
                    const int nt = wn * 4 + ni;
                    bl[ni] = *(const uint2*)(buf + 5120 + (nt * 2 + ks) * 64 + lane * 2);
                }
#pragma unroll
                for (int mi = 0; mi < 4; mi++)
#pragma unroll
                    for (int ni = 0; ni < 4; ni++)
                        mma16(c[mi][ni], ah[mi].x, ah[mi].y, ah[mi].z, ah[mi].w,
                              bl[ni].x, bl[ni].y);
            }
        }
    };

    ldg_chunk(0);
    sts_chunk(smw);
    __syncthreads();
    for (int cc = 0; cc < nchunk; cc++) {
        if (cc + 1 < nchunk) ldg_chunk((cc + 1) << 5);
        mma_chunk(smw + (cc & 1) * 6144);
        if (cc + 1 < nchunk) sts_chunk(smw + ((cc + 1) & 1) * 6144);
        __syncthreads();
    }

    // ---- epilogue ----
    const int bb = bm >> 11;
#pragma unroll
    for (int mi = 0; mi < 4; mi++) {
        const int row = bm + (wm * 4 + mi) * 16 + g;
#pragma unroll
        for (int ni = 0; ni < 4; ni++) {
            const int col = bn + wn * 32 + ni * 8 + 2 * tg;
            float2 v0 = make_float2(c[mi][ni][0], c[mi][ni][1]);
            float2 v1 = make_float2(c[mi][ni][2], c[mi][ni][3]);
            if (colBias) {
                float2 cb = *(const float2*)(colBias + col);
                v0.x += cb.x; v0.y += cb.y;
                v1.x += cb.x; v1.y += cb.y;
            }
            if (batchBias) {
                float2 pb = *(const float2*)(batchBias + (long)bb * N + col);
                v0.x += pb.x; v0.y += pb.y;
                v1.x += pb.x; v1.y += pb.y;
            }
            if (OUTS) {
                uint32_t h, l;
                split_pair(v0.x, v0.y, h, l);
                CS[(long)row * (N >> 1) + (col >> 1)] = make_uint2(h, l);
                split_pair(v1.x, v1.y, h, l);
                CS[(long)(row + 8) * (N >> 1) + (col >> 1)] = make_uint2(h, l);
            } else {
                float* g0 = C + (long)row * N + col;
                float* g1 = C + (long)(row + 8) * N + col;
                if (ACCUM) {
                    float2 o0 = *(const float2*)g0;
                    float2 o1 = *(const float2*)g1;
                    v0.x += o0.x; v0.y += o0.y;
                    v1.x += o1.x; v1.y += o1.y;
                }
                if (RELU) {
                    v0.x = fmaxf(v0.x, 0.f); v0.y = fmaxf(v0.y, 0.f);
                    v1.x = fmaxf(v1.x, 0.f); v1.y = fmaxf(v1.y, 0.f);
                }
                *(float2*)g0 = v0;
                *(float2*)g1 = v1;
            }
        }
    }
}

// ============= flash attention, hi-only everywhere (1-product) ===================
// grid=(NB/64, B*H), 128 threads (4 warps x 16 q-rows). KV tiles of 64 keys.
// QK = Qh*Kh ; PV = Ph*Vh  (residual-damped path).
// smem per buffer (words): Kh[2048] Vh[2048]; double buffered = 32KB.
// occupancy 2 ON PURPOSE: occ 3 thrashed KV L2 reuse in R10 (2396us regression).
#define FLASH_SMEM (2 * 4096 * 4)
__global__ void __launch_bounds__(128, 2) flash_kernel(
    const uint2* __restrict__ QS, const uint2* __restrict__ KVS,
    uint2* __restrict__ OS)
{
    extern __shared__ uint32_t smw[];
    const int tid = threadIdx.x, wid = tid >> 5, lane = tid & 31;
    const int g = lane >> 2, tg = lane & 3;
    const int bh = blockIdx.y, b = bh >> 4, h = bh & 15;
    const int q0 = blockIdx.x * 64;
    const int qrow = q0 + wid * 16;

    uint32_t Qh[4][4];
    {
        const uint2* qb = QS + (long)(b * NB_ + qrow + g) * 512 + h * 32 + tg;
#pragma unroll
        for (int ks = 0; ks < 4; ks++) {
            Qh[ks][0] = qb[ks * 8].x;
            Qh[ks][1] = qb[ks * 8 + 8 * 512].x;
            Qh[ks][2] = qb[ks * 8 + 4].x;
            Qh[ks][3] = qb[ks * 8 + 8 * 512 + 4].x;
        }
    }

    float m0 = -1e30f, m1 = -1e30f, l0 = 0.f, l1 = 0.f;
    float o[8][4];
#pragma unroll
    for (int nt = 0; nt < 8; nt++)
#pragma unroll
        for (int e = 0; e < 4; e++) o[nt][e] = 0.f;

    const uint2* kvb = KVS + (long)b * NCTX * 1024;
    const int vsel = g & 1;

    for (int kt = 0; kt < NCTX; kt += 64) {
        uint32_t* buf = smw + ((kt >> 6) & 1) * 4096;

        // ---- stage K (hi only) ----
#pragma unroll
        for (int i = 0; i < 8; i++) {
            const int gk = wid * 8 + i;
            const int nt = gk >> 2, ks = gk & 3;
            const uint2* kp = kvb + (long)(kt + nt * 8 + g) * 1024 + h * 32 + ks * 8 + tg;
            uint2 u0 = kp[0];
            uint2 u1 = kp[4];
            *(uint2*)(buf + gk * 64 + lane * 2) = make_uint2(u0.x, u1.x);
        }
        // ---- stage V (hi only) ----
#pragma unroll
        for (int i = 0; i < 8; i++) {
            const int gv = wid * 8 + i;
            const int nt = gv >> 2, ks = gv & 3;
            const long r0 = kt + ks * 16 + 2 * tg;
            const int vcol = 512 + h * 32 + nt * 4 + (g >> 1);
            uint2 u0 = kvb[r0 * 1024 + vcol];
            uint2 u1 = kvb[(r0 + 1) * 1024 + vcol];
            uint2 u2 = kvb[(r0 + 8) * 1024 + vcol];
            uint2 u3 = kvb[(r0 + 9) * 1024 + vcol];
            uint32_t hw0 = pick_h(u0.x, vsel) | (pick_h(u1.x, vsel) << 16);
            uint32_t hw1 = pick_h(u2.x, vsel) | (pick_h(u3.x, vsel) << 16);
            *(uint2*)(buf + 2048 + gv * 64 + lane * 2) = make_uint2(hw0, hw1);
        }
        __syncthreads();

        // ---- QK^T : Qh * Kh ----
        float S[8][4];
#pragma unroll
        for (int nt = 0; nt < 8; nt++)
#pragma unroll
            for (int e = 0; e < 4; e++) S[nt][e] = 0.f;

#pragma unroll
        for (int ks = 0; ks < 4; ks++) {
            uint2 kh[8];
#pragma unroll
            for (int nt = 0; nt < 8; nt++)
                kh[nt] = *(const uint2*)(buf + (nt * 4 + ks) * 64 + lane * 2);
#pragma unroll
            for (int nt = 0; nt < 8; nt++)
                mma16(S[nt], Qh[ks][0], Qh[ks][1], Qh[ks][2], Qh[ks][3],
                      kh[nt].x, kh[nt].y);
        }

        // ---- online softmax ----
        float mx0 = -1e30f, mx1 = -1e30f;
#pragma unroll
        for (int nt = 0; nt < 8; nt++) {
            S[nt][0] *= 0.125f; S[nt][1] *= 0.125f;
            S[nt][2] *= 0.125f; S[nt][3] *= 0.125f;
            mx0 = fmaxf(mx0, fmaxf(S[nt][0], S[nt][1]));
            mx1 = fmaxf(mx1, fmaxf(S[nt][2], S[nt][3]));
        }
        mx0 = fmaxf(mx0, __shfl_xor_sync(0xffffffffu, mx0, 1));
        mx0 = fmaxf(mx0, __shfl_xor_sync(0xffffffffu, mx0, 2));
        mx1 = fmaxf(mx1, __shfl_xor_sync(0xffffffffu, mx1, 1));
        mx1 = fmaxf(mx1, __shfl_xor_sync(0xffffffffu, mx1, 2));
        const float mn0 = fmaxf(m0, mx0), mn1 = fmaxf(m1, mx1);
        const float al0 = __expf(m0 - mn0), al1 = __expf(m1 - mn1);
        m0 = mn0; m1 = mn1;
        float s0 = 0.f, s1 = 0.f;
#pragma unroll
        for (int nt = 0; nt < 8; nt++) {
            S[nt][0] = __expf(S[nt][0] - mn0); s0 += S[nt][0];
            S[nt][1] = __expf(S[nt][1] - mn0); s0 += S[nt][1];
            S[nt][2] = __expf(S[nt][2] - mn1); s1 += S[nt][2];
            S[nt][3] = __expf(S[nt][3] - mn1); s1 += S[nt][3];
        }
        s0 += __shfl_xor_sync(0xffffffffu, s0, 1);
        s0 += __shfl_xor_sync(0xffffffffu, s0, 2);
        s1 += __shfl_xor_sync(0xffffffffu, s1, 1);
        s1 += __shfl_xor_sync(0xffffffffu, s1, 2);
        l0 = l0 * al0 + s0;
        l1 = l1 * al1 + s1;
#pragma unroll
        for (int nt = 0; nt < 8; nt++) {
            o[nt][0] *= al0; o[nt][1] *= al0;
            o[nt][2] *= al1; o[nt][3] *= al1;
        }

        // ---- P -> A-fragments (hi only) ----
        uint32_t Ph[4][4];
#pragma unroll
        for (int ks = 0; ks < 4; ks++) {
            Ph[ks][0] = pack_h(S[2 * ks][0], S[2 * ks][1]);
            Ph[ks][1] = pack_h(S[2 * ks][2], S[2 * ks][3]);
            Ph[ks][2] = pack_h(S[2 * ks + 1][0], S[2 * ks + 1][1]);
            Ph[ks][3] = pack_h(S[2 * ks + 1][2], S[2 * ks + 1][3]);
        }

        // ---- P V : Ph * Vh ----
#pragma unroll
        for (int ks = 0; ks < 4; ks++) {
            uint2 vh[8];
#pragma unroll
            for (int nt = 0; nt < 8; nt++)
                vh[nt] = *(const uint2*)(buf + 2048 + (nt * 4 + ks) * 64 + lane * 2);
#pragma unroll
            for (int nt = 0; nt < 8; nt++)
                mma16(o[nt], Ph[ks][0], Ph[ks][1], Ph[ks][2], Ph[ks][3],
                      vh[nt].x, vh[nt].y);
        }
    }

    const float inv0 = 1.0f / l0, inv1 = 1.0f / l1;
    uint2* op0 = OS + (long)(b * NB_ + qrow + g) * 512 + h * 32 + tg;
    uint2* op1 = op0 + 8 * 512;
#pragma unroll
    for (int nt = 0; nt < 8; nt++) {
        uint32_t h0, l0w;
        split_pair(o[nt][0] * inv0, o[nt][1] * inv0, h0, l0w);
        op0[nt * 4] = make_uint2(h0, l0w);
        split_pair(o[nt][2] * inv1, o[nt][3] * inv1, h0, l0w);
        op1[nt * 4] = make_uint2(h0, l0w);
    }
}

// ---------------- residual + layernorm -> split plane ----------------------------
__global__ void __launch_bounds__(256) ln_kernel(
    const float* __restrict__ X, const float* __restrict__ R,
    const float* __restrict__ gam, const float* __restrict__ bet,
    uint2* __restrict__ YS)
{
    __shared__ float red[8];
    const int row = blockIdx.x, tid = threadIdx.x;
    const float2* x = (const float2*)(X + (long)row * D_);
    const float2* rr = (const float2*)(R + (long)row * D_);
    float2 v[2];
    float s = 0.f;
#pragma unroll
    for (int i = 0; i < 2; i++) {
        int p = tid + 256 * i;
        float2 a = x[p], b = rr[p];
        v[i].x = a.x + b.x;
        v[i].y = a.y + b.y;
        s += v[i].x + v[i].y;
    }
#pragma unroll
    for (int off = 16; off > 0; off >>= 1) s += __shfl_xor_sync(0xffffffffu, s, off);
    if ((tid & 31) == 0) red[tid >> 5] = s;
    __syncthreads();
    float tot = red[0] + red[1] + red[2] + red[3] + red[4] + red[5] + red[6] + red[7];
    float mu = tot * (1.0f / 1024.0f);
    __syncthreads();
    float s2 = 0.f;
#pragma unroll
    for (int i = 0; i < 2; i++) {
        float dx = v[i].x - mu, dy = v[i].y - mu;
        s2 += dx * dx + dy * dy;
    }
#pragma unroll
    for (int off = 16; off > 0; off >>= 1) s2 += __shfl_xor_sync(0xffffffffu, s2, off);
    if ((tid & 31) == 0) red[tid >> 5] = s2;
    __syncthreads();
    float tot2 = red[0] + red[1] + red[2] + red[3] + red[4] + red[5] + red[6] + red[7];
    float rstd = rsqrtf(tot2 * (1.0f / 1024.0f) + 1e-5f);
#pragma unroll
    for (int i = 0; i < 2; i++) {
        int p = tid + 256 * i;
        float2 gg = ((const float2*)gam)[p];
        float2 bb = ((const float2*)bet)[p];
        float y0 = (v[i].x - mu) * rstd * gg.x + bb.x;
        float y1 = (v[i].y - mu) * rstd * gg.y + bb.y;
        uint32_t h, l;
        split_pair(y0, y1, h, l);
        YS[(long)row * 512 + p] = make_uint2(h, l);
    }
}

// ---------------- generic warp-dot: Y[b][j] = act(dot(X[b], W[j]) + b1 + b2) ------
template <int ACT>
__global__ void __launch_bounds__(256) rowdot(
    const float* __restrict__ X, const float* __restrict__ W, int ldw,
    const float* __restrict__ b1, const float* __restrict__ b2,
    float* __restrict__ Y, int Kd, int J)
{
    const int b = blockIdx.x;
    const int w = threadIdx.x >> 5, lane = threadIdx.x & 31;
    const int j = blockIdx.y * 8 + w;
    const float* x = X + (long)b * Kd;
    const float* wr = W + (long)j * ldw;
    float s = 0.f;
    for (int k = lane * 4; k < Kd; k += 128) {
        float4 xv = *(const float4*)(x + k);
        float4 wv = *(const float4*)(wr + k);
        s += xv.x * wv.x + xv.y * wv.y + xv.z * wv.z + xv.w * wv.w;
    }
#pragma unroll
    for (int off = 16; off > 0; off >>= 1) s += __shfl_xor_sync(0xffffffffu, s, off);
    if (lane == 0) {
        if (b1) s += b1[j];
        if (b2) s += b2[j];
        if (ACT == 1) s = s / (1.f + expf(-s));
        Y[(long)b * J + j] = s;
    }
}

// ---------------- small kernels ---------------------------------------------------
__global__ void emb_kernel(const int* __restrict__ t)
{
    const int b = blockIdx.x, i = threadIdx.x;
    float fr = expf(-9.2103403719761836f * (float)i / 511.0f);
    float arg = (float)t[b] * fr;
    g_emb[b * D_ + i] = sinf(arg);
    g_emb[b * D_ + 512 + i] = cosf(arg);
}

__global__ void __launch_bounds__(256) router_kernel(
    const float* __restrict__ logits, const int* __restrict__ t,
    float* __restrict__ dispatch, float* __restrict__ combine, float* __restrict__ loadp)
{
    __shared__ float sd[8 * 256];
    const int tid = threadIdx.x;
    const int tok = blockIdx.x * 256 + tid;
    const int b = tok >> 11;
    const float tn = (float)t[b] * 0.001f;
    const float tau_inv = 1.0f / (0.5f + 1.5f * tn);

    float p[8];
    float mx = -1e30f;
#pragma unroll
    for (int e = 0; e < 8; e++) { p[e] = logits[tok * 8 + e] * tau_inv; mx = fmaxf(mx, p[e]); }
    float s = 0.f;
#pragma unroll
    for (int e = 0; e < 8; e++) { p[e] = expf(p[e] - mx); s += p[e]; }
    float inv = 1.0f / s;
#pragma unroll
    for (int e = 0; e < 8; e++) p[e] = 0.85f * (p[e] * inv) + 0.01875f;

    const float w = 0.1f + 0.1f * tn;
    float sh = fmaxf(p[0], w);
    float os = 0.f;
#pragma unroll
    for (int e = 1; e < 8; e++) os += p[e];
    float sc = (1.0f - sh) / fmaxf(os, 1e-8f);
    p[0] = sh;
#pragma unroll
    for (int e = 1; e < 8; e++) p[e] *= sc;

    int i1 = 0; float v1 = p[0];
#pragma unroll
    for (int e = 1; e < 8; e++) if (p[e] > v1) { v1 = p[e]; i1 = e; }
    int i2 = -1; float v2 = -1e30f;
#pragma unroll
    for (int e = 0; e < 8; e++) if (e != i1 && p[e] > v2) { v2 = p[e]; i2 = e; }

    float d[8];
#pragma unroll
    for (int e = 0; e < 8; e++) d[e] = 0.f;
    d[i1] = v1; d[i2] = v2;

    const float cap = 0.5f + 0.1f * tn;
    float ext = 0.f, hs = 0.f;
    float hd[8];
#pragma unroll
    for (int e = 0; e < 8; e++) {
        float ex = fmaxf(d[e] - cap, 0.f);
        d[e] -= ex; ext += ex;
        hd[e] = fmaxf(cap - d[e], 0.f); hs += hd[e];
    }
    hs = fmaxf(hs, 1e-8f);
    float ds = 0.f;
#pragma unroll
    for (int e = 0; e < 8; e++) { d[e] += ext * (hd[e] / hs); ds += d[e]; }
    float ci = 1.0f / (ds + 1e-8f);
#pragma unroll
    for (int e = 0; e < 8; e++) {
        dispatch[tok * 8 + e] = d[e];
        combine[tok * 8 + e] = d[e] * ci;
        sd[e * 256 + tid] = d[e];
    }
    __syncthreads();
    if (tid < 8) {
        float acc = 0.f;
        for (int i = 0; i < 256; i++) acc += sd[tid * 256 + i];
        loadp[blockIdx.x * 8 + tid] = acc;
    }
}

__global__ void penalty_kernel(const float* __restrict__ loadp, float* __restrict__ out)
{
    if (threadIdx.x == 0) {
        const float thr = (2048.0f / 7.0f) * 1.5f;
        float pen = 0.f;
        for (int e = 1; e < 8; e++) {
            float l = 0.f;
            for (int blk = 0; blk < 32; blk++) l += loadp[blk * 8 + e];
            l *= 0.25f;
            float x = l - thr;
            if (x > 0.f) pen += x * x;
        }
        out[0] = 0.01f * pen;
    }
}

// ---------------- launch ----------------------------------------------------------
extern "C" void kernel_launch(void* const* d_in, const int* in_sizes, int n_in,
                              void* d_out, int out_size)
{
    const float* tokens = (const float*)d_in[0];
    const float* outA   = (const float*)d_in[1];
    const float* outC   = (const float*)d_in[2];
    const int*   t      = (const int*)d_in[3];
    const float* in_w   = (const float*)d_in[4];
    const float* in_b   = (const float*)d_in[5];
    const float* op_w   = (const float*)d_in[6];
    const float* op_b   = (const float*)d_in[7];
    const float* lng    = (const float*)d_in[8];
    const float* lnb    = (const float*)d_in[9];
    const float* te_w1  = (const float*)d_in[10];
    const float* te_b1  = (const float*)d_in[11];
    const float* te_w2  = (const float*)d_in[12];
    const float* te_b2  = (const float*)d_in[13];
    const float* gw1    = (const float*)d_in[14];
    const float* gb1    = (const float*)d_in[15];
    const float* gw2    = (const float*)d_in[16];
    const float* gb2    = (const float*)d_in[17];
    const float* ebias  = (const float*)d_in[18];
    float* out = (float*)d_out;

    uint2 *p_tokS, *p_ctxACS, *p_qS, *p_kvS, *p_attnS, *p_ctxBS,
          *p_inwS, *p_opwS, *p_gw1S;
    float *p_proj, *p_hidden, *p_logits, *p_emb, *p_h2, *p_temb, *p_tec, *p_loadp;
    cudaGetSymbolAddress((void**)&p_tokS, g_tokS);
    cudaGetSymbolAddress((void**)&p_ctxACS, g_ctxACS);
    cudaGetSymbolAddress((void**)&p_qS, g_qS);
    cudaGetSymbolAddress((void**)&p_kvS, g_kvS);
    cudaGetSymbolAddress((void**)&p_attnS, g_attnS);
    cudaGetSymbolAddress((void**)&p_ctxBS, g_ctxBS);
    cudaGetSymbolAddress((void**)&p_inwS, g_inwS);
    cudaGetSymbolAddress((void**)&p_opwS, g_opwS);
    cudaGetSymbolAddress((void**)&p_gw1S, g_gw1S);
    cudaGetSymbolAddress((void**)&p_proj, g_proj);
    cudaGetSymbolAddress((void**)&p_hidden, g_hidden);
    cudaGetSymbolAddress((void**)&p_logits, g_logits);
    cudaGetSymbolAddress((void**)&p_emb, g_emb);
    cudaGetSymbolAddress((void**)&p_h2, g_h2);
    cudaGetSymbolAddress((void**)&p_temb, g_temb);
    cudaGetSymbolAddress((void**)&p_tec, g_tec);
    cudaGetSymbolAddress((void**)&p_loadp, g_loadp);

    cudaFuncSetAttribute(flash_kernel, cudaFuncAttributeMaxDynamicSharedMemorySize,
                         FLASH_SMEM);
    cudaFuncSetAttribute(hgemm_nt<2, false, false, true>,
                         cudaFuncAttributeMaxDynamicSharedMemorySize, HGEMM_SMEM);
    cudaFuncSetAttribute(hgemm_nt<1, false, false, false>,
                         cudaFuncAttributeMaxDynamicSharedMemorySize, HGEMM_SMEM);
    cudaFuncSetAttribute(hgemm_nt<3, false, false, false>,
                         cudaFuncAttributeMaxDynamicSharedMemorySize, HGEMM_SMEM);
    cudaFuncSetAttribute(hgemm_nt<3, true, true, false>,
                         cudaFuncAttributeMaxDynamicSharedMemorySize, HGEMM_SMEM);

    // ---- time embedding chain ----
    emb_kernel<<<BATCH, 512>>>(t);
    rowdot<1><<<dim3(BATCH, 256), 256>>>(p_emb, te_w1, 1024, te_b1, nullptr, p_h2, 1024, 2048);
    rowdot<0><<<dim3(BATCH, 128), 256>>>(p_h2, te_w2, 2048, te_b2, nullptr, p_temb, 2048, 1024);
    rowdot<0><<<dim3(BATCH, 128), 256>>>(p_temb, gw1 + 2048, 3072, gb1, nullptr, p_tec, 1024, 1024);

    // ---- split inputs/weights into fp16 hi/lo planes ----
    split_kernel<<<NTOK * 2, 256>>>(tokens, p_tokS);
    split_kernel<<<6144, 256>>>(in_w, p_inwS);
    split_kernel<<<2048, 256>>>(op_w, p_opwS);
    split_kernel<<<6144, 256>>>(gw1, p_gw1S);
    concat_kernel<<<NTOK, 256>>>(outA, outC, p_ctxACS);

    // ---- attention path (residual-damped accuracy budget) ----
    hgemm_nt<2, false, false, true><<<dim3(16, 64), 128, HGEMM_SMEM>>>(
        1024, 1024, p_tokS, 512, p_inwS, 512, nullptr, p_qS, in_b, nullptr);
    hgemm_nt<2, false, false, true><<<dim3(32, 64), 128, HGEMM_SMEM>>>(
        2048, 1024, p_ctxACS, 512, p_inwS + 1024 * 512, 512, nullptr, p_kvS,
        in_b + 1024, nullptr);
    flash_kernel<<<dim3(32, BATCH * H_), 128, FLASH_SMEM>>>(p_qS, p_kvS, p_attnS);
    hgemm_nt<1, false, false, false><<<dim3(16, 64), 128, HGEMM_SMEM>>>(
        1024, 1024, p_attnS, 512, p_opwS, 512, p_proj, nullptr, op_b, nullptr);
    ln_kernel<<<NTOK, 256>>>(p_proj, tokens, lng, lnb, p_ctxBS);

    // ---- gate hidden (3-product: logit-critical) ----
    hgemm_nt<3, false, false, false><<<dim3(16, 64), 128, HGEMM_SMEM>>>(
        1024, 1024, p_tokS, 512, p_gw1S, 1536, p_hidden, nullptr, nullptr, p_tec);
    hgemm_nt<3, true, true, false><<<dim3(16, 64), 128, HGEMM_SMEM>>>(
        1024, 1024, p_ctxBS, 512, p_gw1S + 512, 1536, p_hidden, nullptr, nullptr, nullptr);

    // ---- logits + routing ----
    rowdot<0><<<dim3(NTOK, 1), 256>>>(p_hidden, gw2, 1024, gb2, ebias, p_logits, 1024, 8);
    router_kernel<<<32, 256>>>(p_logits, t, out, out + 65536, p_loadp);
    penalty_kernel<<<1, 32>>>(p_loadp, out + 2 * 65536);
}

// round 12
// speedup vs baseline: 1.5984x; 1.0506x over previous
#include <cuda_runtime.h>
#include <cuda_fp16.h>
#include <math.h>
#include <stdint.h>

#define D_    1024
#define BATCH 4
#define NB_   2048
#define NCTX  2048
#define H_    16
#define HD_   64
#define E_    8
#define NTOK  8192

// ---------------- scratch (device globals; no allocation allowed) ----------------
// Split planes: uint2 {hi half2, lo half2} per column pair.
__device__ uint2 g_tokS[NTOK * 512];
__device__ uint2 g_ctxACS[NTOK * 512];
__device__ uint2 g_qS[NTOK * 512];
__device__ uint2 g_kvS[NTOK * 1024];
__device__ uint2 g_attnS[NTOK * 512];
__device__ uint2 g_ctxBS[NTOK * 512];
__device__ uint2 g_inwS[3072 * 512];
__device__ uint2 g_opwS[1024 * 512];
__device__ uint2 g_gw1S[1024 * 1536];
__device__ float g_proj[NTOK * D_];
__device__ float g_hidden[NTOK * D_];
__device__ float g_logits[NTOK * E_];
__device__ float g_emb[BATCH * D_];
__device__ float g_h2[BATCH * 2 * D_];
__device__ float g_temb[BATCH * D_];
__device__ float g_tec[BATCH * D_];
__device__ float g_loadp[32 * E_];

// ================= fp16 split helpers ============================================
__device__ __forceinline__ void split_pair(float x, float y, uint32_t& hw, uint32_t& lw)
{
    __half2 h = __floats2half2_rn(x, y);
    hw = *reinterpret_cast<uint32_t*>(&h);
    float rx = x - __low2float(h);
    float ry = y - __high2float(h);
    __half2 l = __floats2half2_rn(rx, ry);
    lw = *reinterpret_cast<uint32_t*>(&l);
}
__device__ __forceinline__ uint32_t pack_h(float x, float y)
{
    __half2 h = __floats2half2_rn(x, y);
    return *reinterpret_cast<uint32_t*>(&h);
}
__device__ __forceinline__ void mma16(float* c, uint32_t a0, uint32_t a1, uint32_t a2,
                                      uint32_t a3, uint32_t b0, uint32_t b1)
{
    asm volatile(
        "mma.sync.aligned.m16n8k16.row.col.f32.f16.f16.f32 "
        "{%0,%1,%2,%3},{%4,%5,%6,%7},{%8,%9},{%0,%1,%2,%3};\n"
        : "+f"(c[0]), "+f"(c[1]), "+f"(c[2]), "+f"(c[3])
        : "r"(a0), "r"(a1), "r"(a2), "r"(a3), "r"(b0), "r"(b1));
}
__device__ __forceinline__ uint32_t pick_h(uint32_t w, int sel)
{
    return sel ? (w >> 16) : (w & 0xffffu);
}

// ---------------- fp32 -> split plane converters ---------------------------------
__global__ void __launch_bounds__(256) split_kernel(
    const float* __restrict__ X, uint2* __restrict__ S)
{
    const int i = blockIdx.x * 256 + threadIdx.x;
    float2 x = ((const float2*)X)[i];
    uint32_t h, l;
    split_pair(x.x, x.y, h, l);
    S[i] = make_uint2(h, l);
}

__global__ void __launch_bounds__(256) concat_kernel(
    const float* __restrict__ A, const float* __restrict__ C, uint2* __restrict__ S)
{
    const int row = blockIdx.x;
    const int b = row >> 11, j = row & 2047;
    const float* src = (j < 1024) ? (A + ((long)b * 1024 + j) * D_)
                                  : (C + ((long)b * 1024 + (j - 1024)) * D_);
    uint2* dst = S + (long)row * 512;
    const int idx = threadIdx.x;
    float4 v = ((const float4*)src)[idx];
    uint32_t h0, l0, h1, l1;
    split_pair(v.x, v.y, h0, l0);
    split_pair(v.z, v.w, h1, l1);
    dst[idx * 2] = make_uint2(h0, l0);
    dst[idx * 2 + 1] = make_uint2(h1, l1);
}

// Buffer (uint32 words): Ah[2048] Al[2048] Bh[1024] Bl[1024] = 6144 words; x2 buffers
#define HGEMM_SMEM (2 * 6144 * 4)

// ============= fp16-split mma GEMM on pre-split planes ===========================
// C(MxN) = A(MxK)*B(NxK)^T + epilogue. grid=(N/64, M/128), 128 threads.
// NPROD=3: AhBh + AhBl + AlBh (~2^-22)   NPROD=2: AhBh + AlBh (~2^-12)
// NPROD=1: AhBh (~2^-11; output consumed as fp16-hi downstream, so no loss)
// OUTS=1: write split-plane output CS instead of float C.
template <int NPROD, bool ACCUM, bool RELU, bool OUTS>
__global__ void __launch_bounds__(128, 3) hgemm_nt(
    int N, int K,
    const uint2* __restrict__ AS, int lda2,
    const uint2* __restrict__ BS, int ldb2,
    float* __restrict__ C, uint2* __restrict__ CS,
    const float* __restrict__ colBias,
    const float* __restrict__ batchBias)
{
    extern __shared__ uint32_t smw[];
    const int tid = threadIdx.x, wid = tid >> 5, lane = tid & 31;
    const int g = lane >> 2, tg = lane & 3;
    const int bm = blockIdx.y * 128, bn = blockIdx.x * 64;
    const int wm = wid & 1, wn = wid >> 1;

    float c[4][4][4];
#pragma unroll
    for (int mi = 0; mi < 4; mi++)
#pragma unroll
        for (int ni = 0; ni < 4; ni++)
#pragma unroll
            for (int e = 0; e < 4; e++) c[mi][ni][e] = 0.f;

    uint2 a_st[4][4];
    uint2 b_st[4][2];

    const uint2* Abase = AS + (long)bm * lda2;
    const uint2* Bbase = BS + (long)bn * ldb2;
    const int nchunk = K >> 5;

    auto ldg_chunk = [&](int c0) {
#pragma unroll
        for (int i = 0; i < 4; i++) {
            const int gA = wid * 4 + i;
            const int mt = gA >> 1, ks = gA & 1;
            const uint2* ap = Abase + (long)(mt * 16 + g) * lda2
                              + ((c0 + ks * 16) >> 1) + tg;
            a_st[i][0] = ap[0];
            a_st[i][1] = ap[8 * lda2];
            a_st[i][2] = ap[4];
            a_st[i][3] = ap[8 * lda2 + 4];
        }
#pragma unroll
        for (int i = 0; i < 4; i++) {
            const int gB = wid * 4 + i;
            const int nt = gB >> 1, ks = gB & 1;
            const uint2* bp = Bbase + (long)(nt * 8 + g) * ldb2
                              + ((c0 + ks * 16) >> 1) + tg;
            b_st[i][0] = bp[0];
            b_st[i][1] = bp[4];
        }
    };

    auto sts_chunk = [&](uint32_t* buf) {
#pragma unroll
        for (int i = 0; i < 4; i++) {
            const int gA = wid * 4 + i;
            *(uint4*)(buf + gA * 128 + lane * 4) =
                make_uint4(a_st[i][0].x, a_st[i][1].x, a_st[i][2].x, a_st[i][3].x);
            if (NPROD >= 2)
                *(uint4*)(buf + 2048 + gA * 128 + lane * 4) =
                    make_uint4(a_st[i][0].y, a_st[i][1].y, a_st[i][2].y, a_st[i][3].y);
        }
#pragma unroll
        for (int i = 0; i < 4; i++) {
            const int gB = wid * 4 + i;
            *(uint2*)(buf + 4096 + gB * 64 + lane * 2) =
                make_uint2(b_st[i][0].x, b_st[i][1].x);
            if (NPROD == 3)
                *(uint2*)(buf + 5120 + gB * 64 + lane * 2) =
                    make_uint2(b_st[i][0].y, b_st[i][1].y);
        }
    };

    auto mma_chunk = [&](const uint32_t* buf) {
#pragma unroll
        for (int ks = 0; ks < 2; ks++) {
            uint4 ah[4];
            uint2 bh[4];
#pragma unroll
            for (int mi = 0; mi < 4; mi++) {
                const int mt = wm * 4 + mi;
                ah[mi] = *(const uint4*)(buf + (mt * 2 + ks) * 128 + lane * 4);
            }
#pragma unroll
            for (int ni = 0; ni < 4; ni++) {
                const int nt = wn * 4 + ni;
                bh[ni] = *(const uint2*)(buf + 4096 + (nt * 2 + ks) * 64 + lane * 2);
            }
#pragma unroll
            for (int mi = 0; mi < 4; mi++)
#pragma unroll
                for (int ni = 0; ni < 4; ni++)
                    mma16(c[mi][ni], ah[mi].x, ah[mi].y, ah[mi].z, ah[mi].w,
                          bh[ni].x, bh[ni].y);
            if (NPROD >= 2) {
                uint4 al[4];
#pragma unroll
                for (int mi = 0; mi < 4; mi++) {
                    const int mt = wm * 4 + mi;
                    al[mi] = *(const uint4*)(buf + 2048 + (mt * 2 + ks) * 128 + lane * 4);
                }
#pragma unroll
                for (int mi = 0; mi < 4; mi++)
#pragma unroll
                    for (int ni = 0; ni < 4; ni++)
                        mma16(c[mi][ni], al[mi].x, al[mi].y, al[mi].z, al[mi].w,
                              bh[ni].x, bh[ni].y);
            }
            if (NPROD == 3) {
                uint2 bl[4];
#pragma unroll
                for (int ni = 0; ni < 4; ni++) {
                    const int nt = wn * 4 + ni;
                    bl[ni] = *(const uint2*)(buf + 5120 + (nt * 2 + ks) * 64 + lane * 2);
                }
#pragma unroll
                for (int mi = 0; mi < 4; mi++)
#pragma unroll
                    for (int ni = 0; ni < 4; ni++)
                        mma16(c[mi][ni], ah[mi].x, ah[mi].y, ah[mi].z, ah[mi].w,
                              bl[ni].x, bl[ni].y);
            }
        }
    };

    ldg_chunk(0);
    sts_chunk(smw);
    __syncthreads();
    for (int cc = 0; cc < nchunk; cc++) {
        if (cc + 1 < nchunk) ldg_chunk((cc + 1) << 5);
        mma_chunk(smw + (cc & 1) * 6144);
        if (cc + 1 < nchunk) sts_chunk(smw + ((cc + 1) & 1) * 6144);
        __syncthreads();
    }

    // ---- epilogue ----
    const int bb = bm >> 11;
#pragma unroll
    for (int mi = 0; mi < 4; mi++) {
        const int row = bm + (wm * 4 + mi) * 16 + g;
#pragma unroll
        for (int ni = 0; ni < 4; ni++) {
            const int col = bn + wn * 32 + ni * 8 + 2 * tg;
            float2 v0 = make_float2(c[mi][ni][0], c[mi][ni][1]);
            float2 v1 = make_float2(c[mi][ni][2], c[mi][ni][3]);
            if (colBias) {
                float2 cb = *(const float2*)(colBias + col);
                v0.x += cb.x; v0.y += cb.y;
                v1.x += cb.x; v1.y += cb.y;
            }
            if (batchBias) {
                float2 pb = *(const float2*)(batchBias + (long)bb * N + col);
                v0.x += pb.x; v0.y += pb.y;
                v1.x += pb.x; v1.y += pb.y;
            }
            if (OUTS) {
                uint32_t h, l;
                split_pair(v0.x, v0.y, h, l);
                CS[(long)row * (N >> 1) + (col >> 1)] = make_uint2(h, l);
                split_pair(v1.x, v1.y, h, l);
                CS[(long)(row + 8) * (N >> 1) + (col >> 1)] = make_uint2(h, l);
            } else {
                float* g0 = C + (long)row * N + col;
                float* g1 = C + (long)(row + 8) * N + col;
                if (ACCUM) {
                    float2 o0 = *(const float2*)g0;
                    float2 o1 = *(const float2*)g1;
                    v0.x += o0.x; v0.y += o0.y;
                    v1.x += o1.x; v1.y += o1.y;
                }
                if (RELU) {
                    v0.x = fmaxf(v0.x, 0.f); v0.y = fmaxf(v0.y, 0.f);
                    v1.x = fmaxf(v1.x, 0.f); v1.y = fmaxf(v1.y, 0.f);
                }
                *(float2*)g0 = v0;
                *(float2*)g1 = v1;
            }
        }
    }
}

// ============= flash attention, hi-only everywhere (1-product) ===================
// grid=(NB/64, B*H), 128 threads (4 warps x 16 q-rows). KV tiles of 64 keys.
// QK = Qh*Kh ; PV = Ph*Vh  (residual-damped path).
// smem per buffer (words): Kh[2048] Vh[2048]; double buffered = 32KB.
// occupancy 2 ON PURPOSE: occ 3 thrashed KV L2 reuse in R10 (2396us regression).
#define FLASH_SMEM (2 * 4096 * 4)
__global__ void __launch_bounds__(128, 2) flash_kernel(
    const uint2* __restrict__ QS, const uint2* __restrict__ KVS,
    uint2* __restrict__ OS)
{
    extern __shared__ uint32_t smw[];
    const int tid = threadIdx.x, wid = tid >> 5, lane = tid & 31;
    const int g = lane >> 2, tg = lane & 3;
    const int bh = blockIdx.y, b = bh >> 4, h = bh & 15;
    const int q0 = blockIdx.x * 64;
    const int qrow = q0 + wid * 16;

    uint32_t Qh[4][4];
    {
        const uint2* qb = QS + (long)(b * NB_ + qrow + g) * 512 + h * 32 + tg;
#pragma unroll
        for (int ks = 0; ks < 4; ks++) {
            Qh[ks][0] = qb[ks * 8].x;
            Qh[ks][1] = qb[ks * 8 + 8 * 512].x;
            Qh[ks][2] = qb[ks * 8 + 4].x;
            Qh[ks][3] = qb[ks * 8 + 8 * 512 + 4].x;
        }
    }

    float m0 = -1e30f, m1 = -1e30f, l0 = 0.f, l1 = 0.f;
    float o[8][4];
#pragma unroll
    for (int nt = 0; nt < 8; nt++)
#pragma unroll
        for (int e = 0; e < 4; e++) o[nt][e] = 0.f;

    const uint2* kvb = KVS + (long)b * NCTX * 1024;
    const int vsel = g & 1;

    for (int kt = 0; kt < NCTX; kt += 64) {
        uint32_t* buf = smw + ((kt >> 6) & 1) * 4096;

        // ---- stage K (hi only) ----
#pragma unroll
        for (int i = 0; i < 8; i++) {
            const int gk = wid * 8 + i;
            const int nt = gk >> 2, ks = gk & 3;
            const uint2* kp = kvb + (long)(kt + nt * 8 + g) * 1024 + h * 32 + ks * 8 + tg;
            uint2 u0 = kp[0];
            uint2 u1 = kp[4];
            *(uint2*)(buf + gk * 64 + lane * 2) = make_uint2(u0.x, u1.x);
        }
        // ---- stage V (hi only) ----
#pragma unroll
        for (int i = 0; i < 8; i++) {
            const int gv = wid * 8 + i;
            const int nt = gv >> 2, ks = gv & 3;
            const long r0 = kt + ks * 16 + 2 * tg;
            const int vcol = 512 + h * 32 + nt * 4 + (g >> 1);
            uint2 u0 = kvb[r0 * 1024 + vcol];
            uint2 u1 = kvb[(r0 + 1) * 1024 + vcol];
            uint2 u2 = kvb[(r0 + 8) * 1024 + vcol];
            uint2 u3 = kvb[(r0 + 9) * 1024 + vcol];
            uint32_t hw0 = pick_h(u0.x, vsel) | (pick_h(u1.x, vsel) << 16);
            uint32_t hw1 = pick_h(u2.x, vsel) | (pick_h(u3.x, vsel) << 16);
            *(uint2*)(buf + 2048 + gv * 64 + lane * 2) = make_uint2(hw0, hw1);
        }
        __syncthreads();

        // ---- QK^T : Qh * Kh ----
        float S[8][4];
#pragma unroll
        for (int nt = 0; nt < 8; nt++)
#pragma unroll
            for (int e = 0; e < 4; e++) S[nt][e] = 0.f;

#pragma unroll
        for (int ks = 0; ks < 4; ks++) {
            uint2 kh[8];
#pragma unroll
            for (int nt = 0; nt < 8; nt++)
                kh[nt] = *(const uint2*)(buf + (nt * 4 + ks) * 64 + lane * 2);
#pragma unroll
            for (int nt = 0; nt < 8; nt++)
                mma16(S[nt], Qh[ks][0], Qh[ks][1], Qh[ks][2], Qh[ks][3],
                      kh[nt].x, kh[nt].y);
        }

        // ---- online softmax ----
        float mx0 = -1e30f, mx1 = -1e30f;
#pragma unroll
        for (int nt = 0; nt < 8; nt++) {
            S[nt][0] *= 0.125f; S[nt][1] *= 0.125f;
            S[nt][2] *= 0.125f; S[nt][3] *= 0.125f;
            mx0 = fmaxf(mx0, fmaxf(S[nt][0], S[nt][1]));
            mx1 = fmaxf(mx1, fmaxf(S[nt][2], S[nt][3]));
        }
        mx0 = fmaxf(mx0, __shfl_xor_sync(0xffffffffu, mx0, 1));
        mx0 = fmaxf(mx0, __shfl_xor_sync(0xffffffffu, mx0, 2));
        mx1 = fmaxf(mx1, __shfl_xor_sync(0xffffffffu, mx1, 1));
        mx1 = fmaxf(mx1, __shfl_xor_sync(0xffffffffu, mx1, 2));
        const float mn0 = fmaxf(m0, mx0), mn1 = fmaxf(m1, mx1);
        const float al0 = __expf(m0 - mn0), al1 = __expf(m1 - mn1);
        m0 = mn0; m1 = mn1;
        float s0 = 0.f, s1 = 0.f;
#pragma unroll
        for (int nt = 0; nt < 8; nt++) {
            S[nt][0] = __expf(S[nt][0] - mn0); s0 += S[nt][0];
            S[nt][1] = __expf(S[nt][1] - mn0); s0 += S[nt][1];
            S[nt][2] = __expf(S[nt][2] - mn1); s1 += S[nt][2];
            S[nt][3] = __expf(S[nt][3] - mn1); s1 += S[nt][3];
        }
        s0 += __shfl_xor_sync(0xffffffffu, s0, 1);
        s0 += __shfl_xor_sync(0xffffffffu, s0, 2);
        s1 += __shfl_xor_sync(0xffffffffu, s1, 1);
        s1 += __shfl_xor_sync(0xffffffffu, s1, 2);
        l0 = l0 * al0 + s0;
        l1 = l1 * al1 + s1;
#pragma unroll
        for (int nt = 0; nt < 8; nt++) {
            o[nt][0] *= al0; o[nt][1] *= al0;
            o[nt][2] *= al1; o[nt][3] *= al1;
        }

        // ---- P -> A-fragments (hi only) ----
        uint32_t Ph[4][4];
#pragma unroll
        for (int ks = 0; ks < 4; ks++) {
            Ph[ks][0] = pack_h(S[2 * ks][0], S[2 * ks][1]);
            Ph[ks][1] = pack_h(S[2 * ks][2], S[2 * ks][3]);
            Ph[ks][2] = pack_h(S[2 * ks + 1][0], S[2 * ks + 1][1]);
            Ph[ks][3] = pack_h(S[2 * ks + 1][2], S[2 * ks + 1][3]);
        }

        // ---- P V : Ph * Vh ----
#pragma unroll
        for (int ks = 0; ks < 4; ks++) {
            uint2 vh[8];
#pragma unroll
            for (int nt = 0; nt < 8; nt++)
                vh[nt] = *(const uint2*)(buf + 2048 + (nt * 4 + ks) * 64 + lane * 2);
#pragma unroll
            for (int nt = 0; nt < 8; nt++)
                mma16(o[nt], Ph[ks][0], Ph[ks][1], Ph[ks][2], Ph[ks][3],
                      vh[nt].x, vh[nt].y);
        }
    }

    const float inv0 = 1.0f / l0, inv1 = 1.0f / l1;
    uint2* op0 = OS + (long)(b * NB_ + qrow + g) * 512 + h * 32 + tg;
    uint2* op1 = op0 + 8 * 512;
#pragma unroll
    for (int nt = 0; nt < 8; nt++) {
        uint32_t h0, l0w;
        split_pair(o[nt][0] * inv0, o[nt][1] * inv0, h0, l0w);
        op0[nt * 4] = make_uint2(h0, l0w);
        split_pair(o[nt][2] * inv1, o[nt][3] * inv1, h0, l0w);
        op1[nt * 4] = make_uint2(h0, l0w);
    }
}

// ---------------- residual + layernorm -> split plane ----------------------------
__global__ void __launch_bounds__(256) ln_kernel(
    const float* __restrict__ X, const float* __restrict__ R,
    const float* __restrict__ gam, const float* __restrict__ bet,
    uint2* __restrict__ YS)
{
    __shared__ float red[8];
    const int row = blockIdx.x, tid = threadIdx.x;
    const float2* x = (const float2*)(X + (long)row * D_);
    const float2* rr = (const float2*)(R + (long)row * D_);
    float2 v[2];
    float s = 0.f;
#pragma unroll
    for (int i = 0; i < 2; i++) {
        int p = tid + 256 * i;
        float2 a = x[p], b = rr[p];
        v[i].x = a.x + b.x;
        v[i].y = a.y + b.y;
        s += v[i].x + v[i].y;
    }
#pragma unroll
    for (int off = 16; off > 0; off >>= 1) s += __shfl_xor_sync(0xffffffffu, s, off);
    if ((tid & 31) == 0) red[tid >> 5] = s;
    __syncthreads();
    float tot = red[0] + red[1] + red[2] + red[3] + red[4] + red[5] + red[6] + red[7];
    float mu = tot * (1.0f / 1024.0f);
    __syncthreads();
    float s2 = 0.f;
#pragma unroll
    for (int i = 0; i < 2; i++) {
        float dx = v[i].x - mu, dy = v[i].y - mu;
        s2 += dx * dx + dy * dy;
    }
#pragma unroll
    for (int off = 16; off > 0; off >>= 1) s2 += __shfl_xor_sync(0xffffffffu, s2, off);
    if ((tid & 31) == 0) red[tid >> 5] = s2;
    __syncthreads();
    float tot2 = red[0] + red[1] + red[2] + red[3] + red[4] + red[5] + red[6] + red[7];
    float rstd = rsqrtf(tot2 * (1.0f / 1024.0f) + 1e-5f);
#pragma unroll
    for (int i = 0; i < 2; i++) {
        int p = tid + 256 * i;
        float2 gg = ((const float2*)gam)[p];
        float2 bb = ((const float2*)bet)[p];
        float y0 = (v[i].x - mu) * rstd * gg.x + bb.x;
        float y1 = (v[i].y - mu) * rstd * gg.y + bb.y;
        uint32_t h, l;
        split_pair(y0, y1, h, l);
        YS[(long)row * 512 + p] = make_uint2(h, l);
    }
}

// ---------------- generic warp-dot: Y[b][j] = act(dot(X[b], W[j]) + b1 + b2) ------
template <int ACT>
__global__ void __launch_bounds__(256) rowdot(
    const float* __restrict__ X, const float* __restrict__ W, int ldw,
    const float* __restrict__ b1, const float* __restrict__ b2,
    float* __restrict__ Y, int Kd, int J)
{
    const int b = blockIdx.x;
    const int w = threadIdx.x >> 5, lane = threadIdx.x & 31;
    const int j = blockIdx.y * 8 + w;
    const float* x = X + (long)b * Kd;
    const float* wr = W + (long)j * ldw;
    float s = 0.f;
    for (int k = lane * 4; k < Kd; k += 128) {
        float4 xv = *(const float4*)(x + k);
        float4 wv = *(const float4*)(wr + k);
        s += xv.x * wv.x + xv.y * wv.y + xv.z * wv.z + xv.w * wv.w;
    }
#pragma unroll
    for (int off = 16; off > 0; off >>= 1) s += __shfl_xor_sync(0xffffffffu, s, off);
    if (lane == 0) {
        if (b1) s += b1[j];
        if (b2) s += b2[j];
        if (ACT == 1) s = s / (1.f + expf(-s));
        Y[(long)b * J + j] = s;
    }
}

// ---------------- small kernels ---------------------------------------------------
__global__ void emb_kernel(const int* __restrict__ t)
{
    const int b = blockIdx.x, i = threadIdx.x;
    float fr = expf(-9.2103403719761836f * (float)i / 511.0f);
    float arg = (float)t[b] * fr;
    g_emb[b * D_ + i] = sinf(arg);
    g_emb[b * D_ + 512 + i] = cosf(arg);
}

__global__ void __launch_bounds__(256) router_kernel(
    const float* __restrict__ logits, const int* __restrict__ t,
    float* __restrict__ dispatch, float* __restrict__ combine, float* __restrict__ loadp)
{
    __shared__ float sd[8 * 256];
    const int tid = threadIdx.x;
    const int tok = blockIdx.x * 256 + tid;
    const int b = tok >> 11;
    const float tn = (float)t[b] * 0.001f;
    const float tau_inv = 1.0f / (0.5f + 1.5f * tn);

    float p[8];
    float mx = -1e30f;
#pragma unroll
    for (int e = 0; e < 8; e++) { p[e] = logits[tok * 8 + e] * tau_inv; mx = fmaxf(mx, p[e]); }
    float s = 0.f;
#pragma unroll
    for (int e = 0; e < 8; e++) { p[e] = expf(p[e] - mx); s += p[e]; }
    float inv = 1.0f / s;
#pragma unroll
    for (int e = 0; e < 8; e++) p[e] = 0.85f * (p[e] * inv) + 0.01875f;

    const float w = 0.1f + 0.1f * tn;
    float sh = fmaxf(p[0], w);
    float os = 0.f;
#pragma unroll
    for (int e = 1; e < 8; e++) os += p[e];
    float sc = (1.0f - sh) / fmaxf(os, 1e-8f);
    p[0] = sh;
#pragma unroll
    for (int e = 1; e < 8; e++) p[e] *= sc;

    int i1 = 0; float v1 = p[0];
#pragma unroll
    for (int e = 1; e < 8; e++) if (p[e] > v1) { v1 = p[e]; i1 = e; }
    int i2 = -1; float v2 = -1e30f;
#pragma unroll
    for (int e = 0; e < 8; e++) if (e != i1 && p[e] > v2) { v2 = p[e]; i2 = e; }

    float d[8];
#pragma unroll
    for (int e = 0; e < 8; e++) d[e] = 0.f;
    d[i1] = v1; d[i2] = v2;

    const float cap = 0.5f + 0.1f * tn;
    float ext = 0.f, hs = 0.f;
    float hd[8];
#pragma unroll
    for (int e = 0; e < 8; e++) {
        float ex = fmaxf(d[e] - cap, 0.f);
        d[e] -= ex; ext += ex;
        hd[e] = fmaxf(cap - d[e], 0.f); hs += hd[e];
    }
    hs = fmaxf(hs, 1e-8f);
    float ds = 0.f;
#pragma unroll
    for (int e = 0; e < 8; e++) { d[e] += ext * (hd[e] / hs); ds += d[e]; }
    float ci = 1.0f / (ds + 1e-8f);
#pragma unroll
    for (int e = 0; e < 8; e++) {
        dispatch[tok * 8 + e] = d[e];
        combine[tok * 8 + e] = d[e] * ci;
        sd[e * 256 + tid] = d[e];
    }
    __syncthreads();
    if (tid < 8) {
        float acc = 0.f;
        for (int i = 0; i < 256; i++) acc += sd[tid * 256 + i];
        loadp[blockIdx.x * 8 + tid] = acc;
    }
}

__global__ void penalty_kernel(const float* __restrict__ loadp, float* __restrict__ out)
{
    if (threadIdx.x == 0) {
        const float thr = (2048.0f / 7.0f) * 1.5f;
        float pen = 0.f;
        for (int e = 1; e < 8; e++) {
            float l = 0.f;
            for (int blk = 0; blk < 32; blk++) l += loadp[blk * 8 + e];
            l *= 0.25f;
            float x = l - thr;
            if (x > 0.f) pen += x * x;
        }
        out[0] = 0.01f * pen;
    }
}

// ---------------- launch ----------------------------------------------------------
extern "C" void kernel_launch(void* const* d_in, const int* in_sizes, int n_in,
                              void* d_out, int out_size)
{
    const float* tokens = (const float*)d_in[0];
    const float* outA   = (const float*)d_in[1];
    const float* outC   = (const float*)d_in[2];
    const int*   t      = (const int*)d_in[3];
    const float* in_w   = (const float*)d_in[4];
    const float* in_b   = (const float*)d_in[5];
    const float* op_w   = (const float*)d_in[6];
    const float* op_b   = (const float*)d_in[7];
    const float* lng    = (const float*)d_in[8];
    const float* lnb    = (const float*)d_in[9];
    const float* te_w1  = (const float*)d_in[10];
    const float* te_b1  = (const float*)d_in[11];
    const float* te_w2  = (const float*)d_in[12];
    const float* te_b2  = (const float*)d_in[13];
    const float* gw1    = (const float*)d_in[14];
    const float* gb1    = (const float*)d_in[15];
    const float* gw2    = (const float*)d_in[16];
    const float* gb2    = (const float*)d_in[17];
    const float* ebias  = (const float*)d_in[18];
    float* out = (float*)d_out;

    uint2 *p_tokS, *p_ctxACS, *p_qS, *p_kvS, *p_attnS, *p_ctxBS,
          *p_inwS, *p_opwS, *p_gw1S;
    float *p_proj, *p_hidden, *p_logits, *p_emb, *p_h2, *p_temb, *p_tec, *p_loadp;
    cudaGetSymbolAddress((void**)&p_tokS, g_tokS);
    cudaGetSymbolAddress((void**)&p_ctxACS, g_ctxACS);
    cudaGetSymbolAddress((void**)&p_qS, g_qS);
    cudaGetSymbolAddress((void**)&p_kvS, g_kvS);
    cudaGetSymbolAddress((void**)&p_attnS, g_attnS);
    cudaGetSymbolAddress((void**)&p_ctxBS, g_ctxBS);
    cudaGetSymbolAddress((void**)&p_inwS, g_inwS);
    cudaGetSymbolAddress((void**)&p_opwS, g_opwS);
    cudaGetSymbolAddress((void**)&p_gw1S, g_gw1S);
    cudaGetSymbolAddress((void**)&p_proj, g_proj);
    cudaGetSymbolAddress((void**)&p_hidden, g_hidden);
    cudaGetSymbolAddress((void**)&p_logits, g_logits);
    cudaGetSymbolAddress((void**)&p_emb, g_emb);
    cudaGetSymbolAddress((void**)&p_h2, g_h2);
    cudaGetSymbolAddress((void**)&p_temb, g_temb);
    cudaGetSymbolAddress((void**)&p_tec, g_tec);
    cudaGetSymbolAddress((void**)&p_loadp, g_loadp);

    cudaFuncSetAttribute(flash_kernel, cudaFuncAttributeMaxDynamicSharedMemorySize,
                         FLASH_SMEM);
    cudaFuncSetAttribute(hgemm_nt<1, false, false, true>,
                         cudaFuncAttributeMaxDynamicSharedMemorySize, HGEMM_SMEM);
    cudaFuncSetAttribute(hgemm_nt<1, false, false, false>,
                         cudaFuncAttributeMaxDynamicSharedMemorySize, HGEMM_SMEM);
    cudaFuncSetAttribute(hgemm_nt<3, false, false, false>,
                         cudaFuncAttributeMaxDynamicSharedMemorySize, HGEMM_SMEM);
    cudaFuncSetAttribute(hgemm_nt<3, true, true, false>,
                         cudaFuncAttributeMaxDynamicSharedMemorySize, HGEMM_SMEM);

    // ---- time embedding chain ----
    emb_kernel<<<BATCH, 512>>>(t);
    rowdot<1><<<dim3(BATCH, 256), 256>>>(p_emb, te_w1, 1024, te_b1, nullptr, p_h2, 1024, 2048);
    rowdot<0><<<dim3(BATCH, 128), 256>>>(p_h2, te_w2, 2048, te_b2, nullptr, p_temb, 2048, 1024);
    rowdot<0><<<dim3(BATCH, 128), 256>>>(p_temb, gw1 + 2048, 3072, gb1, nullptr, p_tec, 1024, 1024);

    // ---- split inputs/weights into fp16 hi/lo planes ----
    split_kernel<<<NTOK * 2, 256>>>(tokens, p_tokS);
    split_kernel<<<6144, 256>>>(in_w, p_inwS);
    split_kernel<<<2048, 256>>>(op_w, p_opwS);
    split_kernel<<<6144, 256>>>(gw1, p_gw1S);
    concat_kernel<<<NTOK, 256>>>(outA, outC, p_ctxACS);

    // ---- attention path (residual-damped; outputs consumed as fp16-hi) ----
    hgemm_nt<1, false, false, true><<<dim3(16, 64), 128, HGEMM_SMEM>>>(
        1024, 1024, p_tokS, 512, p_inwS, 512, nullptr, p_qS, in_b, nullptr);
    hgemm_nt<1, false, false, true><<<dim3(32, 64), 128, HGEMM_SMEM>>>(
        2048, 1024, p_ctxACS, 512, p_inwS + 1024 * 512, 512, nullptr, p_kvS,
        in_b + 1024, nullptr);
    flash_kernel<<<dim3(32, BATCH * H_), 128, FLASH_SMEM>>>(p_qS, p_kvS, p_attnS);
    hgemm_nt<1, false, false, false><<<dim3(16, 64), 128, HGEMM_SMEM>>>(
        1024, 1024, p_attnS, 512, p_opwS, 512, p_proj, nullptr, op_b, nullptr);
    ln_kernel<<<NTOK, 256>>>(p_proj, tokens, lng, lnb, p_ctxBS);

    // ---- gate hidden (3-product: logit-critical) ----
    hgemm_nt<3, false, false, false><<<dim3(16, 64), 128, HGEMM_SMEM>>>(
        1024, 1024, p_tokS, 512, p_gw1S, 1536, p_hidden, nullptr, nullptr, p_tec);
    hgemm_nt<3, true, true, false><<<dim3(16, 64), 128, HGEMM_SMEM>>>(
        1024, 1024, p_ctxBS, 512, p_gw1S + 512, 1536, p_hidden, nullptr, nullptr, nullptr);

    // ---- logits + routing ----
    rowdot<0><<<dim3(NTOK, 1), 256>>>(p_hidden, gw2, 1024, gb2, ebias, p_logits, 1024, 8);
    router_kernel<<<32, 256>>>(p_logits, t, out, out + 65536, p_loadp);
    penalty_kernel<<<1, 32>>>(p_loadp, out + 2 * 65536);
}

// round 13
// speedup vs baseline: 1.7257x; 1.0796x over previous
#include <cuda_runtime.h>
#include <cuda_fp16.h>
#include <math.h>
#include <stdint.h>

#define D_    1024
#define BATCH 4
#define NB_   2048
#define NCTX  2048
#define H_    16
#define HD_   64
#define E_    8
#define NTOK  8192

// ---------------- scratch (device globals; no allocation allowed) ----------------
// Split planes: uint2 {hi half2, lo half2} per column pair.
// g_xS: combined [tokens(cols 0-511) | ctxB(cols 512-1023)] planes, row stride 1024.
__device__ uint2 g_xS[NTOK * 1024];
__device__ uint2 g_ctxACS[NTOK * 512];
__device__ uint2 g_qS[NTOK * 512];
__device__ uint2 g_kvS[NTOK * 1024];
__device__ uint2 g_attnS[NTOK * 512];
__device__ uint2 g_inwS[3072 * 512];
__device__ uint2 g_opwS[1024 * 512];
__device__ uint2 g_gw1S[1024 * 1536];
__device__ float g_proj[NTOK * D_];
__device__ float g_hidden[NTOK * D_];
__device__ float g_logits[NTOK * E_];
__device__ float g_emb[BATCH * D_];
__device__ float g_h2[BATCH * 2 * D_];
__device__ float g_temb[BATCH * D_];
__device__ float g_tec[BATCH * D_];
__device__ float g_loadp[32 * E_];

// ================= fp16 split helpers ============================================
__device__ __forceinline__ void split_pair(float x, float y, uint32_t& hw, uint32_t& lw)
{
    __half2 h = __floats2half2_rn(x, y);
    hw = *reinterpret_cast<uint32_t*>(&h);
    float rx = x - __low2float(h);
    float ry = y - __high2float(h);
    __half2 l = __floats2half2_rn(rx, ry);
    lw = *reinterpret_cast<uint32_t*>(&l);
}
__device__ __forceinline__ uint32_t pack_h(float x, float y)
{
    __half2 h = __floats2half2_rn(x, y);
    return *reinterpret_cast<uint32_t*>(&h);
}
__device__ __forceinline__ void mma16(float* c, uint32_t a0, uint32_t a1, uint32_t a2,
                                      uint32_t a3, uint32_t b0, uint32_t b1)
{
    asm volatile(
        "mma.sync.aligned.m16n8k16.row.col.f32.f16.f16.f32 "
        "{%0,%1,%2,%3},{%4,%5,%6,%7},{%8,%9},{%0,%1,%2,%3};\n"
        : "+f"(c[0]), "+f"(c[1]), "+f"(c[2]), "+f"(c[3])
        : "r"(a0), "r"(a1), "r"(a2), "r"(a3), "r"(b0), "r"(b1));
}
__device__ __forceinline__ uint32_t pick_h(uint32_t w, int sel)
{
    return sel ? (w >> 16) : (w & 0xffffu);
}

// ---------------- fp32 -> split plane converters ---------------------------------
__global__ void __launch_bounds__(256) split_kernel(
    const float* __restrict__ X, uint2* __restrict__ S)
{
    const int i = blockIdx.x * 256 + threadIdx.x;
    float2 x = ((const float2*)X)[i];
    uint32_t h, l;
    split_pair(x.x, x.y, h, l);
    S[i] = make_uint2(h, l);
}

// tokens -> first 512 cols of g_xS (row stride 1024)
__global__ void __launch_bounds__(256) split_tok_kernel(
    const float* __restrict__ X, uint2* __restrict__ S)
{
    const int row = blockIdx.x;
    const int idx = threadIdx.x;
    float4 v = ((const float4*)(X + (long)row * D_))[idx];
    uint32_t h0, l0, h1, l1;
    split_pair(v.x, v.y, h0, l0);
    split_pair(v.z, v.w, h1, l1);
    uint2* dst = S + (long)row * 1024;
    dst[idx * 2] = make_uint2(h0, l0);
    dst[idx * 2 + 1] = make_uint2(h1, l1);
}

__global__ void __launch_bounds__(256) concat_kernel(
    const float* __restrict__ A, const float* __restrict__ C, uint2* __restrict__ S)
{
    const int row = blockIdx.x;
    const int b = row >> 11, j = row & 2047;
    const float* src = (j < 1024) ? (A + ((long)b * 1024 + j) * D_)
                                  : (C + ((long)b * 1024 + (j - 1024)) * D_);
    uint2* dst = S + (long)row * 512;
    const int idx = threadIdx.x;
    float4 v = ((const float4*)src)[idx];
    uint32_t h0, l0, h1, l1;
    split_pair(v.x, v.y, h0, l0);
    split_pair(v.z, v.w, h1, l1);
    dst[idx * 2] = make_uint2(h0, l0);
    dst[idx * 2 + 1] = make_uint2(h1, l1);
}

// Buffer (uint32 words): Ah[2048] Al[2048] Bh[1024] Bl[1024] = 6144 words; x2 buffers
#define HGEMM_SMEM (2 * 6144 * 4)

// ============= fp16-split mma GEMM on pre-split planes ===========================
// C(MxN) = A(MxK)*B(NxK)^T + epilogue. grid=(N/64, M/128), 128 threads.
// NPROD=3: AhBh + AhBl + AlBh (~2^-22)   NPROD=2: AhBh + AlBh (~2^-12)
// NPROD=1: AhBh (~2^-11; output consumed as fp16-hi downstream, so no loss)
// OUTS=1: write split-plane output CS instead of float C.
template <int NPROD, bool ACCUM, bool RELU, bool OUTS>
__global__ void __launch_bounds__(128, 3) hgemm_nt(
    int N, int K,
    const uint2* __restrict__ AS, int lda2,
    const uint2* __restrict__ BS, int ldb2,
    float* __restrict__ C, uint2* __restrict__ CS,
    const float* __restrict__ colBias,
    const float* __restrict__ batchBias)
{
    extern __shared__ uint32_t smw[];
    const int tid = threadIdx.x, wid = tid >> 5, lane = tid & 31;
    const int g = lane >> 2, tg = lane & 3;
    const int bm = blockIdx.y * 128, bn = blockIdx.x * 64;
    const int wm = wid & 1, wn = wid >> 1;

    float c[4][4][4];
#pragma unroll
    for (int mi = 0; mi < 4; mi++)
#pragma unroll
        for (int ni = 0; ni < 4; ni++)
#pragma unroll
            for (int e = 0; e < 4; e++) c[mi][ni][e] = 0.f;

    uint2 a_st[4][4];
    uint2 b_st[4][2];

    const uint2* Abase = AS + (long)bm * lda2;
    const uint2* Bbase = BS + (long)bn * ldb2;
    const int nchunk = K >> 5;

    auto ldg_chunk = [&](int c0) {
#pragma unroll
        for (int i = 0; i < 4; i++) {
            const int gA = wid * 4 + i;
            const int mt = gA >> 1, ks = gA & 1;
            const uint2* ap = Abase + (long)(mt * 16 + g) * lda2
                              + ((c0 + ks * 16) >> 1) + tg;
            a_st[i][0] = ap[0];
            a_st[i][1] = ap[8 * lda2];
            a_st[i][2] = ap[4];
            a_st[i][3] = ap[8 * lda2 + 4];
        }
#pragma unroll
        for (int i = 0; i < 4; i++) {
            const int gB = wid * 4 + i;
            const int nt = gB >> 1, ks = gB & 1;
            const uint2* bp = Bbase + (long)(nt * 8 + g) * ldb2
                              + ((c0 + ks * 16) >> 1) + tg;
            b_st[i][0] = bp[0];
            b_st[i][1] = bp[4];
        }
    };

    auto sts_chunk = [&](uint32_t* buf) {
#pragma unroll
        for (int i = 0; i < 4; i++) {
            const int gA = wid * 4 + i;
            *(uint4*)(buf + gA * 128 + lane * 4) =
                make_uint4(a_st[i][0].x, a_st[i][1].x, a_st[i][2].x, a_st[i][3].x);
            if (NPROD >= 2)
                *(uint4*)(buf + 2048 + gA * 128 + lane * 4) =
                    make_uint4(a_st[i][0].y, a_st[i][1].y, a_st[i][2].y, a_st[i][3].y);
        }
#pragma unroll
        for (int i = 0; i < 4; i++) {
            const int gB = wid * 4 + i;
            *(uint2*)(buf + 4096 + gB * 64 + lane * 2) =
                make_uint2(b_st[i][0].x, b_st[i][1].x);
            if (NPROD == 3)
                *(uint2*)(buf + 5120 + gB * 64 + lane * 2) =
                    make_uint2(b_st[i][0].y, b_st[i][1].y);
        }
    };

    auto mma_chunk = [&](const uint32_t* buf) {
#pragma unroll
        for (int ks = 0; ks < 2; ks++) {
            uint4 ah[4];
            uint2 bh[4];
#pragma unroll
            for (int mi = 0; mi < 4; mi++) {
                const int mt = wm * 4 + mi;
                ah[mi] = *(const uint4*)(buf + (mt * 2 + ks) * 128 + lane * 4);
            }
#pragma unroll
            for (int ni = 0; ni < 4; ni++) {
                const int nt = wn * 4 + ni;
                bh[ni] = *(const uint2*)(buf + 4096 + (nt * 2 + ks) * 64 + lane * 2);
            }
#pragma unroll
            for (int mi = 0; mi < 4; mi++)
#pragma unroll
                for (int ni = 0; ni < 4; ni++)
                    mma16(c[mi][ni], ah[mi].x, ah[mi].y, ah[mi].z, ah[mi].w,
                          bh[ni].x, bh[ni].y);
            if (NPROD >= 2) {
                uint4 al[4];
#pragma unroll
                for (int mi = 0; mi < 4; mi++) {
                    const int mt = wm * 4 + mi;
                    al[mi] = *(const uint4*)(buf + 2048 + (mt * 2 + ks) * 128 + lane * 4);
                }
#pragma unroll
                for (int mi = 0; mi < 4; mi++)
#pragma unroll
                    for (int ni = 0; ni < 4; ni++)
                        mma16(c[mi][ni], al[mi].x, al[mi].y, al[mi].z, al[mi].w,
                              bh[ni].x, bh[ni].y);
            }
            if (NPROD == 3) {
                uint2 bl[4];
#pragma unroll
                for (int ni = 0; ni < 4; ni++) {
                    const int nt = wn * 4 + ni;
                    bl[ni] = *(const uint2*)(buf + 5120 + (nt * 2 + ks) * 64 + lane * 2);
                }
#pragma unroll
                for (int mi = 0; mi < 4; mi++)
#pragma unroll
                    for (int ni = 0; ni < 4; ni++)
                        mma16(c[mi][ni], ah[mi].x, ah[mi].y, ah[mi].z, ah[mi].w,
                              bl[ni].x, bl[ni].y);
            }
        }
    };

    ldg_chunk(0);
    sts_chunk(smw);
    __syncthreads();
    for (int cc = 0; cc < nchunk; cc++) {
        if (cc + 1 < nchunk) ldg_chunk((cc + 1) << 5);
        mma_chunk(smw + (cc & 1) * 6144);
        if (cc + 1 < nchunk) sts_chunk(smw + ((cc + 1) & 1) * 6144);
        __syncthreads();
    }

    // ---- epilogue ----
    const int bb = bm >> 11;
#pragma unroll
    for (int mi = 0; mi < 4; mi++) {
        const int row = bm + (wm * 4 + mi) * 16 + g;
#pragma unroll
        for (int ni = 0; ni < 4; ni++) {
            const int col = bn + wn * 32 + ni * 8 + 2 * tg;
            float2 v0 = make_float2(c[mi][ni][0], c[mi][ni][1]);
            float2 v1 = make_float2(c[mi][ni][2], c[mi][ni][3]);
            if (colBias) {
                float2 cb = *(const float2*)(colBias + col);
                v0.x += cb.x; v0.y += cb.y;
                v1.x += cb.x; v1.y += cb.y;
            }
            if (batchBias) {
                float2 pb = *(const float2*)(batchBias + (long)bb * N + col);
                v0.x += pb.x; v0.y += pb.y;
                v1.x += pb.x; v1.y += pb.y;
            }
            if (OUTS) {
                uint32_t h, l;
                split_pair(v0.x, v0.y, h, l);
                CS[(long)row * (N >> 1) + (col >> 1)] = make_uint2(h, l);
                split_pair(v1.x, v1.y, h, l);
                CS[(long)(row + 8) * (N >> 1) + (col >> 1)] = make_uint2(h, l);
            } else {
                float* g0 = C + (long)row * N + col;
                float* g1 = C + (long)(row + 8) * N + col;
                if (ACCUM) {
                    float2 o0 = *(const float2*)g0;
                    float2 o1 = *(const float2*)g1;
                    v0.x += o0.x; v0.y += o0.y;
                    v1.x += o1.x; v1.y += o1.y;
                }
                if (RELU) {
                    v0.x = fmaxf(v0.x, 0.f); v0.y = fmaxf(v0.y, 0.f);
                    v1.x = fmaxf(v1.x, 0.f); v1.y = fmaxf(v1.y, 0.f);
                }
                *(float2*)g0 = v0;
                *(float2*)g1 = v1;
            }
        }
    }
}

// ============= flash attention, hi-only, 128 q-rows per CTA ======================
// grid=(NB/128, B*H), 256 threads (8 warps x 16 q-rows). KV tiles of 64 keys.
// QK = Qh*Kh ; PV = Ph*Vh  (residual-damped path).
// smem per buffer (words): Kh[2048] Vh[2048]; double buffered = 32KB.
// 2 KV streams per SM (occ 2) — matches R11's verified L2-friendly concurrency.
#define FLASH_SMEM (2 * 4096 * 4)
__global__ void __launch_bounds__(256, 2) flash_kernel(
    const uint2* __restrict__ QS, const uint2* __restrict__ KVS,
    uint2* __restrict__ OS)
{
    extern __shared__ uint32_t smw[];
    const int tid = threadIdx.x, wid = tid >> 5, lane = tid & 31;
    const int g = lane >> 2, tg = lane & 3;
    const int bh = blockIdx.y, b = bh >> 4, h = bh & 15;
    const int q0 = blockIdx.x * 128;
    const int qrow = q0 + wid * 16;

    uint32_t Qh[4][4];
    {
        const uint2* qb = QS + (long)(b * NB_ + qrow + g) * 512 + h * 32 + tg;
#pragma unroll
        for (int ks = 0; ks < 4; ks++) {
            Qh[ks][0] = qb[ks * 8].x;
            Qh[ks][1] = qb[ks * 8 + 8 * 512].x;
            Qh[ks][2] = qb[ks * 8 + 4].x;
            Qh[ks][3] = qb[ks * 8 + 8 * 512 + 4].x;
        }
    }

    float m0 = -1e30f, m1 = -1e30f, l0 = 0.f, l1 = 0.f;
    float o[8][4];
#pragma unroll
    for (int nt = 0; nt < 8; nt++)
#pragma unroll
        for (int e = 0; e < 4; e++) o[nt][e] = 0.f;

    const uint2* kvb = KVS + (long)b * NCTX * 1024;
    const int vsel = g & 1;

    for (int kt = 0; kt < NCTX; kt += 64) {
        uint32_t* buf = smw + ((kt >> 6) & 1) * 4096;

        // ---- stage K (hi only): 32 groups over 8 warps ----
#pragma unroll
        for (int i = 0; i < 4; i++) {
            const int gk = wid * 4 + i;
            const int nt = gk >> 2, ks = gk & 3;
            const uint2* kp = kvb + (long)(kt + nt * 8 + g) * 1024 + h * 32 + ks * 8 + tg;
            uint2 u0 = kp[0];
            uint2 u1 = kp[4];
            *(uint2*)(buf + gk * 64 + lane * 2) = make_uint2(u0.x, u1.x);
        }
        // ---- stage V (hi only) ----
#pragma unroll
        for (int i = 0; i < 4; i++) {
            const int gv = wid * 4 + i;
            const int nt = gv >> 2, ks = gv & 3;
            const long r0 = kt + ks * 16 + 2 * tg;
            const int vcol = 512 + h * 32 + nt * 4 + (g >> 1);
            uint2 u0 = kvb[r0 * 1024 + vcol];
            uint2 u1 = kvb[(r0 + 1) * 1024 + vcol];
            uint2 u2 = kvb[(r0 + 8) * 1024 + vcol];
            uint2 u3 = kvb[(r0 + 9) * 1024 + vcol];
            uint32_t hw0 = pick_h(u0.x, vsel) | (pick_h(u1.x, vsel) << 16);
            uint32_t hw1 = pick_h(u2.x, vsel) | (pick_h(u3.x, vsel) << 16);
            *(uint2*)(buf + 2048 + gv * 64 + lane * 2) = make_uint2(hw0, hw1);
        }
        __syncthreads();

        // ---- QK^T : Qh * Kh ----
        float S[8][4];
#pragma unroll
        for (int nt = 0; nt < 8; nt++)
#pragma unroll
            for (int e = 0; e < 4; e++) S[nt][e] = 0.f;

#pragma unroll
        for (int ks = 0; ks < 4; ks++) {
            uint2 kh[8];
#pragma unroll
            for (int nt = 0; nt < 8; nt++)
                kh[nt] = *(const uint2*)(buf + (nt * 4 + ks) * 64 + lane * 2);
#pragma unroll
            for (int nt = 0; nt < 8; nt++)
                mma16(S[nt], Qh[ks][0], Qh[ks][1], Qh[ks][2], Qh[ks][3],
                      kh[nt].x, kh[nt].y);
        }

        // ---- online softmax ----
        float mx0 = -1e30f, mx1 = -1e30f;
#pragma unroll
        for (int nt = 0; nt < 8; nt++) {
            S[nt][0] *= 0.125f; S[nt][1] *= 0.125f;
            S[nt][2] *= 0.125f; S[nt][3] *= 0.125f;
            mx0 = fmaxf(mx0, fmaxf(S[nt][0], S[nt][1]));
            mx1 = fmaxf(mx1, fmaxf(S[nt][2], S[nt][3]));
        }
        mx0 = fmaxf(mx0, __shfl_xor_sync(0xffffffffu, mx0, 1));
        mx0 = fmaxf(mx0, __shfl_xor_sync(0xffffffffu, mx0, 2));
        mx1 = fmaxf(mx1, __shfl_xor_sync(0xffffffffu, mx1, 1));
        mx1 = fmaxf(mx1, __shfl_xor_sync(0xffffffffu, mx1, 2));
        const float mn0 = fmaxf(m0, mx0), mn1 = fmaxf(m1, mx1);
        const float al0 = __expf(m0 - mn0), al1 = __expf(m1 - mn1);
        m0 = mn0; m1 = mn1;
        float s0 = 0.f, s1 = 0.f;
#pragma unroll
        for (int nt = 0; nt < 8; nt++) {
            S[nt][0] = __expf(S[nt][0] - mn0); s0 += S[nt][0];
            S[nt][1] = __expf(S[nt][1] - mn0); s0 += S[nt][1];
            S[nt][2] = __expf(S[nt][2] - mn1); s1 += S[nt][2];
            S[nt][3] = __expf(S[nt][3] - mn1); s1 += S[nt][3];
        }
        s0 += __shfl_xor_sync(0xffffffffu, s0, 1);
        s0 += __shfl_xor_sync(0xffffffffu, s0, 2);
        s1 += __shfl_xor_sync(0xffffffffu, s1, 1);
        s1 += __shfl_xor_sync(0xffffffffu, s1, 2);
        l0 = l0 * al0 + s0;
        l1 = l1 * al1 + s1;
#pragma unroll
        for (int nt = 0; nt < 8; nt++) {
            o[nt][0] *= al0; o[nt][1] *= al0;
            o[nt][2] *= al1; o[nt][3] *= al1;
        }

        // ---- P -> A-fragments (hi only) ----
        uint32_t Ph[4][4];
#pragma unroll
        for (int ks = 0; ks < 4; ks++) {
            Ph[ks][0] = pack_h(S[2 * ks][0], S[2 * ks][1]);
            Ph[ks][1] = pack_h(S[2 * ks][2], S[2 * ks][3]);
            Ph[ks][2] = pack_h(S[2 * ks + 1][0], S[2 * ks + 1][1]);
            Ph[ks][3] = pack_h(S[2 * ks + 1][2], S[2 * ks + 1][3]);
        }

        // ---- P V : Ph * Vh ----
#pragma unroll
        for (int ks = 0; ks < 4; ks++) {
            uint2 vh[8];
#pragma unroll
            for (int nt = 0; nt < 8; nt++)
                vh[nt] = *(const uint2*)(buf + 2048 + (nt * 4 + ks) * 64 + lane * 2);
#pragma unroll
            for (int nt = 0; nt < 8; nt++)
                mma16(o[nt], Ph[ks][0], Ph[ks][1], Ph[ks][2], Ph[ks][3],
                      vh[nt].x, vh[nt].y);
        }
    }

    const float inv0 = 1.0f / l0, inv1 = 1.0f / l1;
    uint2* op0 = OS + (long)(b * NB_ + qrow + g) * 512 + h * 32 + tg;
    uint2* op1 = op0 + 8 * 512;
#pragma unroll
    for (int nt = 0; nt < 8; nt++) {
        uint32_t h0, l0w;
        split_pair(o[nt][0] * inv0, o[nt][1] * inv0, h0, l0w);
        op0[nt * 4] = make_uint2(h0, l0w);
        split_pair(o[nt][2] * inv1, o[nt][3] * inv1, h0, l0w);
        op1[nt * 4] = make_uint2(h0, l0w);
    }
}

// ---------------- residual + layernorm -> g_xS second half ------------------------
__global__ void __launch_bounds__(256) ln_kernel(
    const float* __restrict__ X, const float* __restrict__ R,
    const float* __restrict__ gam, const float* __restrict__ bet,
    uint2* __restrict__ YS)
{
    __shared__ float red[8];
    const int row = blockIdx.x, tid = threadIdx.x;
    const float2* x = (const float2*)(X + (long)row * D_);
    const float2* rr = (const float2*)(R + (long)row * D_);
    float2 v[2];
    float s = 0.f;
#pragma unroll
    for (int i = 0; i < 2; i++) {
        int p = tid + 256 * i;
        float2 a = x[p], b = rr[p];
        v[i].x = a.x + b.x;
        v[i].y = a.y + b.y;
        s += v[i].x + v[i].y;
    }
#pragma unroll
    for (int off = 16; off > 0; off >>= 1) s += __shfl_xor_sync(0xffffffffu, s, off);
    if ((tid & 31) == 0) red[tid >> 5] = s;
    __syncthreads();
    float tot = red[0] + red[1] + red[2] + red[3] + red[4] + red[5] + red[6] + red[7];
    float mu = tot * (1.0f / 1024.0f);
    __syncthreads();
    float s2 = 0.f;
#pragma unroll
    for (int i = 0; i < 2; i++) {
        float dx = v[i].x - mu, dy = v[i].y - mu;
        s2 += dx * dx + dy * dy;
    }
#pragma unroll
    for (int off = 16; off > 0; off >>= 1) s2 += __shfl_xor_sync(0xffffffffu, s2, off);
    if ((tid & 31) == 0) red[tid >> 5] = s2;
    __syncthreads();
    float tot2 = red[0] + red[1] + red[2] + red[3] + red[4] + red[5] + red[6] + red[7];
    float rstd = rsqrtf(tot2 * (1.0f / 1024.0f) + 1e-5f);
#pragma unroll
    for (int i = 0; i < 2; i++) {
        int p = tid + 256 * i;
        float2 gg = ((const float2*)gam)[p];
        float2 bb = ((const float2*)bet)[p];
        float y0 = (v[i].x - mu) * rstd * gg.x + bb.x;
        float y1 = (v[i].y - mu) * rstd * gg.y + bb.y;
        uint32_t h, l;
        split_pair(y0, y1, h, l);
        YS[(long)row * 1024 + 512 + p] = make_uint2(h, l);   // ctxB half of g_xS
    }
}

// ---------------- generic warp-dot: Y[b][j] = act(dot(X[b], W[j]) + b1 + b2) ------
template <int ACT>
__global__ void __launch_bounds__(256) rowdot(
    const float* __restrict__ X, const float* __restrict__ W, int ldw,
    const float* __restrict__ b1, const float* __restrict__ b2,
    float* __restrict__ Y, int Kd, int J)
{
    const int b = blockIdx.x;
    const int w = threadIdx.x >> 5, lane = threadIdx.x & 31;
    const int j = blockIdx.y * 8 + w;
    const float* x = X + (long)b * Kd;
    const float* wr = W + (long)j * ldw;
    float s = 0.f;
    for (int k = lane * 4; k < Kd; k += 128) {
        float4 xv = *(const float4*)(x + k);
        float4 wv = *(const float4*)(wr + k);
        s += xv.x * wv.x + xv.y * wv.y + xv.z * wv.z + xv.w * wv.w;
    }
#pragma unroll
    for (int off = 16; off > 0; off >>= 1) s += __shfl_xor_sync(0xffffffffu, s, off);
    if (lane == 0) {
        if (b1) s += b1[j];
        if (b2) s += b2[j];
        if (ACT == 1) s = s / (1.f + expf(-s));
        Y[(long)b * J + j] = s;
    }
}

// ---------------- small kernels ---------------------------------------------------
__global__ void emb_kernel(const int* __restrict__ t)
{
    const int b = blockIdx.x, i = threadIdx.x;
    float fr = expf(-9.2103403719761836f * (float)i / 511.0f);
    float arg = (float)t[b] * fr;
    g_emb[b * D_ + i] = sinf(arg);
    g_emb[b * D_ + 512 + i] = cosf(arg);
}

__global__ void __launch_bounds__(256) router_kernel(
    const float* __restrict__ logits, const int* __restrict__ t,
    float* __restrict__ dispatch, float* __restrict__ combine, float* __restrict__ loadp)
{
    __shared__ float sd[8 * 256];
    const int tid = threadIdx.x;
    const int tok = blockIdx.x * 256 + tid;
    const int b = tok >> 11;
    const float tn = (float)t[b] * 0.001f;
    const float tau_inv = 1.0f / (0.5f + 1.5f * tn);

    float p[8];
    float mx = -1e30f;
#pragma unroll
    for (int e = 0; e < 8; e++) { p[e] = logits[tok * 8 + e] * tau_inv; mx = fmaxf(mx, p[e]); }
    float s = 0.f;
#pragma unroll
    for (int e = 0; e < 8; e++) { p[e] = expf(p[e] - mx); s += p[e]; }
    float inv = 1.0f / s;
#pragma unroll
    for (int e = 0; e < 8; e++) p[e] = 0.85f * (p[e] * inv) + 0.01875f;

    const float w = 0.1f + 0.1f * tn;
    float sh = fmaxf(p[0], w);
    float os = 0.f;
#pragma unroll
    for (int e = 1; e < 8; e++) os += p[e];
    float sc = (1.0f - sh) / fmaxf(os, 1e-8f);
    p[0] = sh;
#pragma unroll
    for (int e = 1; e < 8; e++) p[e] *= sc;

    int i1 = 0; float v1 = p[0];
#pragma unroll
    for (int e = 1; e < 8; e++) if (p[e] > v1) { v1 = p[e]; i1 = e; }
    int i2 = -1; float v2 = -1e30f;
#pragma unroll
    for (int e = 0; e < 8; e++) if (e != i1 && p[e] > v2) { v2 = p[e]; i2 = e; }

    float d[8];
#pragma unroll
    for (int e = 0; e < 8; e++) d[e] = 0.f;
    d[i1] = v1; d[i2] = v2;

    const float cap = 0.5f + 0.1f * tn;
    float ext = 0.f, hs = 0.f;
    float hd[8];
#pragma unroll
    for (int e = 0; e < 8; e++) {
        float ex = fmaxf(d[e] - cap, 0.f);
        d[e] -= ex; ext += ex;
        hd[e] = fmaxf(cap - d[e], 0.f); hs += hd[e];
    }
    hs = fmaxf(hs, 1e-8f);
    float ds = 0.f;
#pragma unroll
    for (int e = 0; e < 8; e++) { d[e] += ext * (hd[e] / hs); ds += d[e]; }
    float ci = 1.0f / (ds + 1e-8f);
#pragma unroll
    for (int e = 0; e < 8; e++) {
        dispatch[tok * 8 + e] = d[e];
        combine[tok * 8 + e] = d[e] * ci;
        sd[e * 256 + tid] = d[e];
    }
    __syncthreads();
    if (tid < 8) {
        float acc = 0.f;
        for (int i = 0; i < 256; i++) acc += sd[tid * 256 + i];
        loadp[blockIdx.x * 8 + tid] = acc;
    }
}

__global__ void penalty_kernel(const float* __restrict__ loadp, float* __restrict__ out)
{
    if (threadIdx.x == 0) {
        const float thr = (2048.0f / 7.0f) * 1.5f;
        float pen = 0.f;
        for (int e = 1; e < 8; e++) {
            float l = 0.f;
            for (int blk = 0; blk < 32; blk++) l += loadp[blk * 8 + e];
            l *= 0.25f;
            float x = l - thr;
            if (x > 0.f) pen += x * x;
        }
        out[0] = 0.01f * pen;
    }
}

// ---------------- launch ----------------------------------------------------------
extern "C" void kernel_launch(void* const* d_in, const int* in_sizes, int n_in,
                              void* d_out, int out_size)
{
    const float* tokens = (const float*)d_in[0];
    const float* outA   = (const float*)d_in[1];
    const float* outC   = (const float*)d_in[2];
    const int*   t      = (const int*)d_in[3];
    const float* in_w   = (const float*)d_in[4];
    const float* in_b   = (const float*)d_in[5];
    const float* op_w   = (const float*)d_in[6];
    const float* op_b   = (const float*)d_in[7];
    const float* lng    = (const float*)d_in[8];
    const float* lnb    = (const float*)d_in[9];
    const float* te_w1  = (const float*)d_in[10];
    const float* te_b1  = (const float*)d_in[11];
    const float* te_w2  = (const float*)d_in[12];
    const float* te_b2  = (const float*)d_in[13];
    const float* gw1    = (const float*)d_in[14];
    const float* gb1    = (const float*)d_in[15];
    const float* gw2    = (const float*)d_in[16];
    const float* gb2    = (const float*)d_in[17];
    const float* ebias  = (const float*)d_in[18];
    float* out = (float*)d_out;

    uint2 *p_xS, *p_ctxACS, *p_qS, *p_kvS, *p_attnS, *p_inwS, *p_opwS, *p_gw1S;
    float *p_proj, *p_hidden, *p_logits, *p_emb, *p_h2, *p_temb, *p_tec, *p_loadp;
    cudaGetSymbolAddress((void**)&p_xS, g_xS);
    cudaGetSymbolAddress((void**)&p_ctxACS, g_ctxACS);
    cudaGetSymbolAddress((void**)&p_qS, g_qS);
    cudaGetSymbolAddress((void**)&p_kvS, g_kvS);
    cudaGetSymbolAddress((void**)&p_attnS, g_attnS);
    cudaGetSymbolAddress((void**)&p_inwS, g_inwS);
    cudaGetSymbolAddress((void**)&p_opwS, g_opwS);
    cudaGetSymbolAddress((void**)&p_gw1S, g_gw1S);
    cudaGetSymbolAddress((void**)&p_proj, g_proj);
    cudaGetSymbolAddress((void**)&p_hidden, g_hidden);
    cudaGetSymbolAddress((void**)&p_logits, g_logits);
    cudaGetSymbolAddress((void**)&p_emb, g_emb);
    cudaGetSymbolAddress((void**)&p_h2, g_h2);
    cudaGetSymbolAddress((void**)&p_temb, g_temb);
    cudaGetSymbolAddress((void**)&p_tec, g_tec);
    cudaGetSymbolAddress((void**)&p_loadp, g_loadp);

    cudaFuncSetAttribute(flash_kernel, cudaFuncAttributeMaxDynamicSharedMemorySize,
                         FLASH_SMEM);
    cudaFuncSetAttribute(hgemm_nt<1, false, false, true>,
                         cudaFuncAttributeMaxDynamicSharedMemorySize, HGEMM_SMEM);
    cudaFuncSetAttribute(hgemm_nt<1, false, false, false>,
                         cudaFuncAttributeMaxDynamicSharedMemorySize, HGEMM_SMEM);
    cudaFuncSetAttribute(hgemm_nt<3, false, true, false>,
                         cudaFuncAttributeMaxDynamicSharedMemorySize, HGEMM_SMEM);

    // ---- time embedding chain ----
    emb_kernel<<<BATCH, 512>>>(t);
    rowdot<1><<<dim3(BATCH, 256), 256>>>(p_emb, te_w1, 1024, te_b1, nullptr, p_h2, 1024, 2048);
    rowdot<0><<<dim3(BATCH, 128), 256>>>(p_h2, te_w2, 2048, te_b2, nullptr, p_temb, 2048, 1024);
    rowdot<0><<<dim3(BATCH, 128), 256>>>(p_temb, gw1 + 2048, 3072, gb1, nullptr, p_tec, 1024, 1024);

    // ---- split inputs/weights into fp16 hi/lo planes ----
    split_tok_kernel<<<NTOK, 256>>>(tokens, p_xS);
    split_kernel<<<6144, 256>>>(in_w, p_inwS);
    split_kernel<<<2048, 256>>>(op_w, p_opwS);
    split_kernel<<<6144, 256>>>(gw1, p_gw1S);
    concat_kernel<<<NTOK, 256>>>(outA, outC, p_ctxACS);

    // ---- attention path (residual-damped; outputs consumed as fp16-hi) ----
    hgemm_nt<1, false, false, true><<<dim3(16, 64), 128, HGEMM_SMEM>>>(
        1024, 1024, p_xS, 1024, p_inwS, 512, nullptr, p_qS, in_b, nullptr);
    hgemm_nt<1, false, false, true><<<dim3(32, 64), 128, HGEMM_SMEM>>>(
        2048, 1024, p_ctxACS, 512, p_inwS + 1024 * 512, 512, nullptr, p_kvS,
        in_b + 1024, nullptr);
    flash_kernel<<<dim3(16, BATCH * H_), 256, FLASH_SMEM>>>(p_qS, p_kvS, p_attnS);
    hgemm_nt<1, false, false, false><<<dim3(16, 64), 128, HGEMM_SMEM>>>(
        1024, 1024, p_attnS, 512, p_opwS, 512, p_proj, nullptr, op_b, nullptr);
    ln_kernel<<<NTOK, 256>>>(p_proj, tokens, lng, lnb, p_xS);

    // ---- fused gate hidden (K=2048 over [tokens|ctxB]; 3-product) ----
    hgemm_nt<3, false, true, false><<<dim3(16, 64), 128, HGEMM_SMEM>>>(
        1024, 2048, p_xS, 1024, p_gw1S, 1536, p_hidden, nullptr, nullptr, p_tec);

    // ---- logits + routing ----
    rowdot<0><<<dim3(NTOK, 1), 256>>>(p_hidden, gw2, 1024, gb2, ebias, p_logits, 1024, 8);
    router_kernel<<<32, 256>>>(p_logits, t, out, out + 65536, p_loadp);
    penalty_kernel<<<1, 32>>>(p_loadp, out + 2 * 65536);
}